// round 1
// baseline (speedup 1.0000x reference)
#include <cuda_runtime.h>
#include <cuda_bf16.h>
#include <math.h>

// ---------------- problem constants ----------------
#define Bq   16
#define LQ   1024
#define Dm   256
#define Hh   8
#define Ll   4
#define Pp   4
#define DFF  1024
#define DH   32
#define LV   5440
#define M1   (Bq*LQ)       // 16384
#define MV   (Bq*LV)       // 87040
#define EPSV 1e-5f

// ---------------- scratch (static device, no allocs) ----------------
__device__ float g_q   [M1*Dm];        // q = x + pos (reused for q2)
__device__ float g_qk  [M1*512];       // [Q | K] projected, ld=512
__device__ float g_v   [M1*Dm];        // V projected
__device__ float g_att [M1*Dm];        // attention output
__device__ float g_tmp [M1*Dm];        // generic gemm output
__device__ float g_tgt [M1*Dm];        // tgt after norm2
__device__ float g_tgt2[M1*Dm];        // tgt after norm1
__device__ float g_value[(size_t)MV*Dm];
__device__ float g_off [M1*256];
__device__ float g_attw[M1*128];
__device__ float g_samp[M1*Dm];
__device__ float g_ffn [M1*DFF];

// ---------------- elementwise add ----------------
__global__ void add_kernel(const float* __restrict__ a, const float* __restrict__ b,
                           float* __restrict__ c, int n4) {
    int i = blockIdx.x * blockDim.x + threadIdx.x;
    if (i < n4) {
        float4 av = ((const float4*)a)[i];
        float4 bv = ((const float4*)b)[i];
        float4 cv = make_float4(av.x+bv.x, av.y+bv.y, av.z+bv.z, av.w+bv.w);
        ((float4*)c)[i] = cv;
    }
}

// ---------------- generic tiled GEMM: C = A(MxK) @ W(NxK)^T + bias, optional relu ----------------
#define BM 64
#define BN 64
#define BK 16
__global__ __launch_bounds__(256) void gemm_kernel(
    const float* __restrict__ A, const float* __restrict__ W,
    const float* __restrict__ bias, float* __restrict__ C,
    int M, int N, int K, int relu)
{
    __shared__ float As[BK][BM];
    __shared__ float Ws[BK][BN];
    int tid = threadIdx.x;
    int tx = tid & 15, ty = tid >> 4;
    int m0 = blockIdx.y * BM, n0 = blockIdx.x * BN;

    int lr = tid >> 2;       // 0..63
    int lk = tid & 3;        // 0..3 (float4 within 16)

    float acc[4][4];
    #pragma unroll
    for (int i = 0; i < 4; i++)
        #pragma unroll
        for (int j = 0; j < 4; j++) acc[i][j] = 0.f;

    for (int kt = 0; kt < K; kt += BK) {
        float4 av = *((const float4*)(A + (size_t)(m0 + lr) * K + kt) + lk);
        float4 wv = *((const float4*)(W + (size_t)(n0 + lr) * K + kt) + lk);
        As[lk*4+0][lr] = av.x; As[lk*4+1][lr] = av.y;
        As[lk*4+2][lr] = av.z; As[lk*4+3][lr] = av.w;
        Ws[lk*4+0][lr] = wv.x; Ws[lk*4+1][lr] = wv.y;
        Ws[lk*4+2][lr] = wv.z; Ws[lk*4+3][lr] = wv.w;
        __syncthreads();
        #pragma unroll
        for (int k = 0; k < BK; k++) {
            float4 a4 = *(const float4*)&As[k][ty*4];
            float4 b4 = *(const float4*)&Ws[k][tx*4];
            float ar[4] = {a4.x, a4.y, a4.z, a4.w};
            float br[4] = {b4.x, b4.y, b4.z, b4.w};
            #pragma unroll
            for (int i = 0; i < 4; i++)
                #pragma unroll
                for (int j = 0; j < 4; j++)
                    acc[i][j] += ar[i] * br[j];
        }
        __syncthreads();
    }

    int n = n0 + tx*4;
    float4 b4 = *(const float4*)(bias + n);
    #pragma unroll
    for (int i = 0; i < 4; i++) {
        int m = m0 + ty*4 + i;
        float4 c;
        c.x = acc[i][0] + b4.x; c.y = acc[i][1] + b4.y;
        c.z = acc[i][2] + b4.z; c.w = acc[i][3] + b4.w;
        if (relu) {
            c.x = fmaxf(c.x, 0.f); c.y = fmaxf(c.y, 0.f);
            c.z = fmaxf(c.z, 0.f); c.w = fmaxf(c.w, 0.f);
        }
        *(float4*)(C + (size_t)m * N + n) = c;
    }
}

// ---------------- flash attention (64 queries/block, 1 thread = 1 query) ----------------
#define AT 64
__global__ __launch_bounds__(64) void attn_kernel(
    const float* __restrict__ QK, const float* __restrict__ V, float* __restrict__ O)
{
    __shared__ float Ks[AT][32];
    __shared__ float Vs[AT][32];
    __shared__ float Ss[AT][AT + 1];
    int t = threadIdx.x;
    int bh = blockIdx.y, b = bh >> 3, h = bh & 7;
    int q = blockIdx.x * AT + t;

    const float4* qp = (const float4*)(QK + ((size_t)(b*LQ + q))*512 + h*DH);
    float4 qv[8];
    #pragma unroll
    for (int i = 0; i < 8; i++) qv[i] = qp[i];

    float o[32];
    #pragma unroll
    for (int i = 0; i < 32; i++) o[i] = 0.f;
    float m = -1e30f, l = 0.f;
    const float scale = 0.17677669529663687f; // 1/sqrt(32)

    for (int kc = 0; kc < LQ; kc += AT) {
        const float4* kp = (const float4*)(QK + ((size_t)(b*LQ + kc + t))*512 + 256 + h*DH);
        const float4* vp = (const float4*)(V  + ((size_t)(b*LQ + kc + t))*Dm  + h*DH);
        #pragma unroll
        for (int i = 0; i < 8; i++) {
            ((float4*)Ks[t])[i] = kp[i];
            ((float4*)Vs[t])[i] = vp[i];
        }
        __syncthreads();

        float cmax = -1e30f;
        #pragma unroll 4
        for (int j = 0; j < AT; j++) {
            const float4* kk = (const float4*)Ks[j];
            float d = 0.f;
            #pragma unroll
            for (int i = 0; i < 8; i++) {
                float4 kv = kk[i];
                d += qv[i].x*kv.x + qv[i].y*kv.y + qv[i].z*kv.z + qv[i].w*kv.w;
            }
            d *= scale;
            Ss[t][j] = d;
            cmax = fmaxf(cmax, d);
        }
        float mnew = fmaxf(m, cmax);
        float corr = __expf(m - mnew);
        l *= corr;
        #pragma unroll
        for (int i = 0; i < 32; i++) o[i] *= corr;

        #pragma unroll 2
        for (int j = 0; j < AT; j++) {
            float p = __expf(Ss[t][j] - mnew);
            l += p;
            const float* vv = Vs[j];
            #pragma unroll
            for (int i = 0; i < 32; i++) o[i] += p * vv[i];
        }
        m = mnew;
        __syncthreads();
    }

    float inv = 1.f / l;
    float* op = O + ((size_t)(b*LQ + q))*Dm + h*DH;
    #pragma unroll
    for (int i = 0; i < 32; i++) op[i] = o[i] * inv;
}

// ---------------- layernorm(a + b) * g + beta ----------------
__global__ __launch_bounds__(256) void ln_kernel(
    const float* __restrict__ a, const float* __restrict__ b,
    const float* __restrict__ g, const float* __restrict__ be,
    float* __restrict__ out)
{
    __shared__ float red[8];
    int row = blockIdx.x, t = threadIdx.x;
    float x = a[(size_t)row*Dm + t] + b[(size_t)row*Dm + t];

    float s = x;
    #pragma unroll
    for (int o = 16; o; o >>= 1) s += __shfl_xor_sync(0xffffffffu, s, o);
    if ((t & 31) == 0) red[t >> 5] = s;
    __syncthreads();
    float tot = 0.f;
    #pragma unroll
    for (int i = 0; i < 8; i++) tot += red[i];
    float mean = tot * (1.f / Dm);
    float d0 = x - mean;
    __syncthreads();

    float sq = d0 * d0;
    #pragma unroll
    for (int o = 16; o; o >>= 1) sq += __shfl_xor_sync(0xffffffffu, sq, o);
    if ((t & 31) == 0) red[t >> 5] = sq;
    __syncthreads();
    float tot2 = 0.f;
    #pragma unroll
    for (int i = 0; i < 8; i++) tot2 += red[i];
    float var = tot2 * (1.f / Dm);

    out[(size_t)row*Dm + t] = d0 * rsqrtf(var + EPSV) * g[t] + be[t];
}

// ---------------- deformable sampler (attw softmax fused) ----------------
__global__ __launch_bounds__(256) void sampler_kernel(
    const float* __restrict__ refp,   // (B,LQ,L,2)
    const float* __restrict__ off,    // (B*LQ,256)
    const float* __restrict__ attw,   // (B*LQ,128)
    const float* __restrict__ value,  // (B*LV, 256)
    float* __restrict__ samp)         // (B*LQ, 256)
{
    int bq = blockIdx.x;
    int b = bq >> 10;             // / LQ
    int t = threadIdx.x;
    int h = t >> 5, lane = t & 31;

    // --- attw softmax over 16 logits per (b,q,h) ---
    float logit = (lane < 16) ? attw[(size_t)bq*128 + h*16 + lane] : -1e30f;
    float mx = logit;
    #pragma unroll
    for (int o = 16; o; o >>= 1) mx = fmaxf(mx, __shfl_xor_sync(0xffffffffu, mx, o));
    float e = (lane < 16) ? __expf(logit - mx) : 0.f;
    float sum = e;
    #pragma unroll
    for (int o = 16; o; o >>= 1) sum += __shfl_xor_sync(0xffffffffu, sum, o);
    float aw_lane = e / sum;

    const int wls[4]    = {64, 32, 16, 8};
    const int hls[4]    = {64, 32, 16, 8};
    const int starts[4] = {0, 4096, 5120, 5376};

    const float* rp = refp + ((size_t)bq * Ll) * 2;
    float acc = 0.f;

    #pragma unroll
    for (int l = 0; l < Ll; l++) {
        int wl = wls[l], hl = hls[l], st = starts[l];
        float rx = rp[l*2 + 0];
        float ry = rp[l*2 + 1];
        #pragma unroll
        for (int p = 0; p < Pp; p++) {
            int n = (h*Ll + l)*Pp + p;
            float ox = off[(size_t)bq*256 + n*2 + 0];
            float oy = off[(size_t)bq*256 + n*2 + 1];
            float locx = rx + ox / (float)wl;
            float locy = ry + oy / (float)hl;
            float x = locx * (float)wl - 0.5f;
            float y = locy * (float)hl - 0.5f;
            float x0f = floorf(x), y0f = floorf(y);
            float lx = x - x0f, ly = y - y0f;
            int x0 = (int)x0f, y0 = (int)y0f;
            float aw = __shfl_sync(0xffffffffu, aw_lane, l*Pp + p);

            float g00 = 0.f, g01 = 0.f, g10 = 0.f, g11 = 0.f;
            {
                int xi = x0, yi = y0;
                if (xi >= 0 && xi < wl && yi >= 0 && yi < hl)
                    g00 = value[((size_t)(b*LV + st + yi*wl + xi))*Dm + h*DH + lane];
            }
            {
                int xi = x0+1, yi = y0;
                if (xi >= 0 && xi < wl && yi >= 0 && yi < hl)
                    g01 = value[((size_t)(b*LV + st + yi*wl + xi))*Dm + h*DH + lane];
            }
            {
                int xi = x0, yi = y0+1;
                if (xi >= 0 && xi < wl && yi >= 0 && yi < hl)
                    g10 = value[((size_t)(b*LV + st + yi*wl + xi))*Dm + h*DH + lane];
            }
            {
                int xi = x0+1, yi = y0+1;
                if (xi >= 0 && xi < wl && yi >= 0 && yi < hl)
                    g11 = value[((size_t)(b*LV + st + yi*wl + xi))*Dm + h*DH + lane];
            }
            float sv = g00*(1.f-lx)*(1.f-ly) + g01*lx*(1.f-ly)
                     + g10*(1.f-lx)*ly       + g11*lx*ly;
            acc += aw * sv;
        }
    }
    samp[(size_t)bq*Dm + h*DH + lane] = acc;
}

// ---------------- launch ----------------
extern "C" void kernel_launch(void* const* d_in, const int* in_sizes, int n_in,
                              void* d_out, int out_size) {
    const float* tgt  = (const float*)d_in[0];
    const float* qpos = (const float*)d_in[1];
    const float* refp = (const float*)d_in[2];
    const float* src  = (const float*)d_in[3];
    const float* in_w = (const float*)d_in[4];
    const float* in_b = (const float*)d_in[5];
    const float* ow   = (const float*)d_in[6];
    const float* ob   = (const float*)d_in[7];
    const float* n2g  = (const float*)d_in[8];
    const float* n2b  = (const float*)d_in[9];
    const float* vw   = (const float*)d_in[10];
    const float* vb   = (const float*)d_in[11];
    const float* offw = (const float*)d_in[12];
    const float* offb = (const float*)d_in[13];
    const float* aww  = (const float*)d_in[14];
    const float* awb  = (const float*)d_in[15];
    const float* opw  = (const float*)d_in[16];
    const float* opb  = (const float*)d_in[17];
    const float* n1g  = (const float*)d_in[18];
    const float* n1b  = (const float*)d_in[19];
    const float* l1w  = (const float*)d_in[20];
    const float* l1b  = (const float*)d_in[21];
    const float* l2w  = (const float*)d_in[22];
    const float* l2b  = (const float*)d_in[23];
    const float* n3g  = (const float*)d_in[24];
    const float* n3b  = (const float*)d_in[25];
    float* out = (float*)d_out;

    float *p_q, *p_qk, *p_v, *p_att, *p_tmp, *p_tgt, *p_tgt2,
          *p_value, *p_off, *p_attw, *p_samp, *p_ffn;
    cudaGetSymbolAddress((void**)&p_q,    g_q);
    cudaGetSymbolAddress((void**)&p_qk,   g_qk);
    cudaGetSymbolAddress((void**)&p_v,    g_v);
    cudaGetSymbolAddress((void**)&p_att,  g_att);
    cudaGetSymbolAddress((void**)&p_tmp,  g_tmp);
    cudaGetSymbolAddress((void**)&p_tgt,  g_tgt);
    cudaGetSymbolAddress((void**)&p_tgt2, g_tgt2);
    cudaGetSymbolAddress((void**)&p_value,g_value);
    cudaGetSymbolAddress((void**)&p_off,  g_off);
    cudaGetSymbolAddress((void**)&p_attw, g_attw);
    cudaGetSymbolAddress((void**)&p_samp, g_samp);
    cudaGetSymbolAddress((void**)&p_ffn,  g_ffn);

    const int n4 = M1 * Dm / 4;

    // 1. q = tgt + query_pos
    add_kernel<<<(n4 + 255)/256, 256>>>(tgt, qpos, p_q, n4);
    // 2. [Q|K] = q @ in_w[0:512].T + b
    gemm_kernel<<<dim3(512/BN, M1/BM), 256>>>(p_q, in_w, in_b, p_qk, M1, 512, Dm, 0);
    // 3. V = tgt @ in_w[512:768].T + b
    gemm_kernel<<<dim3(Dm/BN, M1/BM), 256>>>(tgt, in_w + 512*Dm, in_b + 512, p_v, M1, Dm, Dm, 0);
    // 4. attention
    attn_kernel<<<dim3(LQ/AT, Bq*Hh), AT>>>(p_qk, p_v, p_att);
    // 5. out_proj
    gemm_kernel<<<dim3(Dm/BN, M1/BM), 256>>>(p_att, ow, ob, p_tmp, M1, Dm, Dm, 0);
    // 6. tgt = LN(tgt + tgt2, norm2)
    ln_kernel<<<M1, 256>>>(tgt, p_tmp, n2g, n2b, p_tgt);
    // 7. q2 = tgt + query_pos
    add_kernel<<<(n4 + 255)/256, 256>>>(p_tgt, qpos, p_q, n4);
    // 8. value = src @ value_w.T + b
    gemm_kernel<<<dim3(Dm/BN, MV/BM), 256>>>(src, vw, vb, p_value, MV, Dm, Dm, 0);
    // 9. off = q2 @ off_w.T + off_b
    gemm_kernel<<<dim3(256/BN, M1/BM), 256>>>(p_q, offw, offb, p_off, M1, 256, Dm, 0);
    // 10. attw logits = q2 @ attw_w.T + attw_b
    gemm_kernel<<<dim3(128/BN, M1/BM), 256>>>(p_q, aww, awb, p_attw, M1, 128, Dm, 0);
    // 11. sampler
    sampler_kernel<<<M1, 256>>>(refp, p_off, p_attw, p_value, p_samp);
    // 12. outp proj
    gemm_kernel<<<dim3(Dm/BN, M1/BM), 256>>>(p_samp, opw, opb, p_tmp, M1, Dm, Dm, 0);
    // 13. tgt = LN(tgt + tgt2, norm1)
    ln_kernel<<<M1, 256>>>(p_tgt, p_tmp, n1g, n1b, p_tgt2);
    // 14. ffn mid = relu(tgt @ lin1.T + b)
    gemm_kernel<<<dim3(DFF/BN, M1/BM), 256>>>(p_tgt2, l1w, l1b, p_ffn, M1, DFF, Dm, 1);
    // 15. ffn out
    gemm_kernel<<<dim3(Dm/BN, M1/BM), 256>>>(p_ffn, l2w, l2b, p_tmp, M1, Dm, DFF, 0);
    // 16. out = LN(tgt + t2, norm3)
    ln_kernel<<<M1, 256>>>(p_tgt2, p_tmp, n3g, n3b, out);
}

// round 2
// speedup vs baseline: 1.8124x; 1.8124x over previous
#include <cuda_runtime.h>
#include <cuda_bf16.h>
#include <math.h>

// ---------------- problem constants ----------------
#define Bq   16
#define LQ   1024
#define Dm   256
#define Hh   8
#define Ll   4
#define Pp   4
#define DFF  1024
#define DH   32
#define LV   5440
#define M1   (Bq*LQ)       // 16384
#define MV   (Bq*LV)       // 87040
#define EPSV 1e-5f

// ---------------- scratch (static device, no allocs) ----------------
__device__ float g_q   [M1*Dm];
__device__ float g_qk  [M1*512];
__device__ float g_v   [M1*Dm];
__device__ float g_att [M1*Dm];
__device__ float g_tmp [M1*Dm];
__device__ float g_tgt [M1*Dm];
__device__ float g_tgt2[M1*Dm];
__device__ float g_value[(size_t)MV*Dm];
__device__ float g_off [M1*256];
__device__ float g_attw[M1*128];
__device__ float g_samp[M1*Dm];
__device__ float g_ffn [M1*DFF];

// ---------------- elementwise add ----------------
__global__ void add_kernel(const float* __restrict__ a, const float* __restrict__ b,
                           float* __restrict__ c, int n4) {
    int i = blockIdx.x * blockDim.x + threadIdx.x;
    if (i < n4) {
        float4 av = ((const float4*)a)[i];
        float4 bv = ((const float4*)b)[i];
        ((float4*)c)[i] = make_float4(av.x+bv.x, av.y+bv.y, av.z+bv.z, av.w+bv.w);
    }
}

// ---------------- SGEMM: C = A(MxK) @ W(NxK)^T + bias, optional relu ----------------
// 128x64 tile, BK=16, 256 threads, 8x4 micro-tile, double-buffered smem.
#define GBM 128
#define GBN 64
#define GBK 16
__global__ __launch_bounds__(256) void gemm_kernel(
    const float* __restrict__ A, const float* __restrict__ W,
    const float* __restrict__ bias, float* __restrict__ C,
    int M, int N, int K, int relu)
{
    __shared__ float As[2][GBK][GBM];   // 2*16*128*4 = 16 KB
    __shared__ float Ws[2][GBK][GBN];   // 2*16*64*4  =  8 KB

    const int tid = threadIdx.x;
    const int tx = tid & 15;            // 0..15 -> 4-col group
    const int ty = tid >> 4;            // 0..15 -> 8-row group
    const int m0 = blockIdx.y * GBM;
    const int n0 = blockIdx.x * GBN;

    // A stage mapping: 512 float4 per tile, 2 per thread
    const int ar0 = tid & 127;          // row for phase 0/1
    const int ak0 = tid >> 7;           // 0..1  (phase 0), +2 in phase 1
    // W stage mapping: 256 float4 per tile, 1 per thread
    const int wr  = tid & 63;
    const int wk  = tid >> 6;           // 0..3

    const float* Aip = A + (size_t)(m0 + ar0) * K;
    const float* Wip = W + (size_t)(n0 + wr ) * K;

    float acc[8][4];
    #pragma unroll
    for (int i = 0; i < 8; i++)
        #pragma unroll
        for (int j = 0; j < 4; j++) acc[i][j] = 0.f;

    // ---- preload tile 0 into buffer 0 ----
    {
        float4 a0 = *((const float4*)Aip + ak0);
        float4 a1 = *((const float4*)Aip + ak0 + 2);
        float4 w0 = *((const float4*)Wip + wk);
        As[0][ak0*4+0][ar0] = a0.x; As[0][ak0*4+1][ar0] = a0.y;
        As[0][ak0*4+2][ar0] = a0.z; As[0][ak0*4+3][ar0] = a0.w;
        As[0][(ak0+2)*4+0][ar0] = a1.x; As[0][(ak0+2)*4+1][ar0] = a1.y;
        As[0][(ak0+2)*4+2][ar0] = a1.z; As[0][(ak0+2)*4+3][ar0] = a1.w;
        Ws[0][wk*4+0][wr] = w0.x; Ws[0][wk*4+1][wr] = w0.y;
        Ws[0][wk*4+2][wr] = w0.z; Ws[0][wk*4+3][wr] = w0.w;
    }
    __syncthreads();

    int buf = 0;
    for (int kt = GBK; kt <= K; kt += GBK) {
        float4 pa0, pa1, pw0;
        const bool more = (kt < K);
        if (more) {
            pa0 = *((const float4*)(Aip + kt) + ak0);
            pa1 = *((const float4*)(Aip + kt) + ak0 + 2);
            pw0 = *((const float4*)(Wip + kt) + wk);
        }

        #pragma unroll
        for (int k = 0; k < GBK; k++) {
            float4 a0 = *(const float4*)&As[buf][k][ty*8];
            float4 a1 = *(const float4*)&As[buf][k][ty*8+4];
            float4 b  = *(const float4*)&Ws[buf][k][tx*4];
            float ar[8] = {a0.x,a0.y,a0.z,a0.w,a1.x,a1.y,a1.z,a1.w};
            float br[4] = {b.x,b.y,b.z,b.w};
            #pragma unroll
            for (int i = 0; i < 8; i++)
                #pragma unroll
                for (int j = 0; j < 4; j++)
                    acc[i][j] = fmaf(ar[i], br[j], acc[i][j]);
        }

        if (more) {
            int nb = buf ^ 1;
            As[nb][ak0*4+0][ar0] = pa0.x; As[nb][ak0*4+1][ar0] = pa0.y;
            As[nb][ak0*4+2][ar0] = pa0.z; As[nb][ak0*4+3][ar0] = pa0.w;
            As[nb][(ak0+2)*4+0][ar0] = pa1.x; As[nb][(ak0+2)*4+1][ar0] = pa1.y;
            As[nb][(ak0+2)*4+2][ar0] = pa1.z; As[nb][(ak0+2)*4+3][ar0] = pa1.w;
            Ws[nb][wk*4+0][wr] = pw0.x; Ws[nb][wk*4+1][wr] = pw0.y;
            Ws[nb][wk*4+2][wr] = pw0.z; Ws[nb][wk*4+3][wr] = pw0.w;
            __syncthreads();
            buf = nb;
        }
    }

    const int n = n0 + tx*4;
    float4 b4 = *(const float4*)(bias + n);
    #pragma unroll
    for (int i = 0; i < 8; i++) {
        int m = m0 + ty*8 + i;
        float4 c;
        c.x = acc[i][0] + b4.x; c.y = acc[i][1] + b4.y;
        c.z = acc[i][2] + b4.z; c.w = acc[i][3] + b4.w;
        if (relu) {
            c.x = fmaxf(c.x, 0.f); c.y = fmaxf(c.y, 0.f);
            c.z = fmaxf(c.z, 0.f); c.w = fmaxf(c.w, 0.f);
        }
        *(float4*)(C + (size_t)m * N + n) = c;
    }
}

// ---------------- flash attention (128 queries/block, key chunks of 32) ----------------
#define ATQ 128
#define KC  32
__global__ __launch_bounds__(ATQ) void attn_kernel(
    const float* __restrict__ QK, const float* __restrict__ V, float* __restrict__ O)
{
    __shared__ float Ks[KC][32];
    __shared__ float Vs[KC][32];
    __shared__ float Ss[ATQ][KC + 1];
    const int t = threadIdx.x;
    const int bh = blockIdx.y, b = bh >> 3, h = bh & 7;
    const int q = blockIdx.x * ATQ + t;

    const float4* qp = (const float4*)(QK + ((size_t)(b*LQ + q))*512 + h*DH);
    float4 qv[8];
    #pragma unroll
    for (int i = 0; i < 8; i++) qv[i] = qp[i];

    float o[32];
    #pragma unroll
    for (int i = 0; i < 32; i++) o[i] = 0.f;
    float m = -1e30f, l = 0.f;
    const float scale = 0.17677669529663687f; // 1/sqrt(32)

    // K/V staging: KC*8 = 256 float4 each, 128 threads -> 2 each
    const int sr0 = t >> 3;        // 0..15 row (phase adds 16)
    const int sc  = t & 7;         // float4 col

    for (int kc = 0; kc < LQ; kc += KC) {
        #pragma unroll
        for (int ph = 0; ph < 2; ph++) {
            int row = sr0 + ph*16;
            const float4* kp = (const float4*)(QK + ((size_t)(b*LQ + kc + row))*512 + 256 + h*DH);
            const float4* vp = (const float4*)(V  + ((size_t)(b*LQ + kc + row))*Dm  + h*DH);
            *((float4*)Ks[row] + sc) = kp[sc];
            *((float4*)Vs[row] + sc) = vp[sc];
        }
        __syncthreads();

        float cmax = -1e30f;
        #pragma unroll 8
        for (int j = 0; j < KC; j++) {
            const float4* kk = (const float4*)Ks[j];
            float d = 0.f;
            #pragma unroll
            for (int i = 0; i < 8; i++) {
                float4 kv = kk[i];
                d += qv[i].x*kv.x + qv[i].y*kv.y + qv[i].z*kv.z + qv[i].w*kv.w;
            }
            d *= scale;
            Ss[t][j] = d;
            cmax = fmaxf(cmax, d);
        }
        float mnew = fmaxf(m, cmax);
        float corr = __expf(m - mnew);
        l *= corr;
        #pragma unroll
        for (int i = 0; i < 32; i++) o[i] *= corr;

        #pragma unroll 4
        for (int j = 0; j < KC; j++) {
            float p = __expf(Ss[t][j] - mnew);
            l += p;
            const float* vv = Vs[j];
            #pragma unroll
            for (int i = 0; i < 32; i++) o[i] = fmaf(p, vv[i], o[i]);
        }
        m = mnew;
        __syncthreads();
    }

    float inv = 1.f / l;
    float* op = O + ((size_t)(b*LQ + q))*Dm + h*DH;
    #pragma unroll
    for (int i = 0; i < 32; i++) op[i] = o[i] * inv;
}

// ---------------- layernorm(a + b) * g + beta ----------------
__global__ __launch_bounds__(256) void ln_kernel(
    const float* __restrict__ a, const float* __restrict__ b,
    const float* __restrict__ g, const float* __restrict__ be,
    float* __restrict__ out)
{
    __shared__ float red[8];
    int row = blockIdx.x, t = threadIdx.x;
    float x = a[(size_t)row*Dm + t] + b[(size_t)row*Dm + t];

    float s = x;
    #pragma unroll
    for (int o = 16; o; o >>= 1) s += __shfl_xor_sync(0xffffffffu, s, o);
    if ((t & 31) == 0) red[t >> 5] = s;
    __syncthreads();
    float tot = 0.f;
    #pragma unroll
    for (int i = 0; i < 8; i++) tot += red[i];
    float mean = tot * (1.f / Dm);
    float d0 = x - mean;
    __syncthreads();

    float sq = d0 * d0;
    #pragma unroll
    for (int o = 16; o; o >>= 1) sq += __shfl_xor_sync(0xffffffffu, sq, o);
    if ((t & 31) == 0) red[t >> 5] = sq;
    __syncthreads();
    float tot2 = 0.f;
    #pragma unroll
    for (int i = 0; i < 8; i++) tot2 += red[i];
    float var = tot2 * (1.f / Dm);

    out[(size_t)row*Dm + t] = d0 * rsqrtf(var + EPSV) * g[t] + be[t];
}

// ---------------- deformable sampler (attw softmax fused) ----------------
__global__ __launch_bounds__(256) void sampler_kernel(
    const float* __restrict__ refp,
    const float* __restrict__ off,
    const float* __restrict__ attw,
    const float* __restrict__ value,
    float* __restrict__ samp)
{
    int bq = blockIdx.x;
    int b = bq >> 10;
    int t = threadIdx.x;
    int h = t >> 5, lane = t & 31;

    float logit = (lane < 16) ? attw[(size_t)bq*128 + h*16 + lane] : -1e30f;
    float mx = logit;
    #pragma unroll
    for (int o = 16; o; o >>= 1) mx = fmaxf(mx, __shfl_xor_sync(0xffffffffu, mx, o));
    float e = (lane < 16) ? __expf(logit - mx) : 0.f;
    float sum = e;
    #pragma unroll
    for (int o = 16; o; o >>= 1) sum += __shfl_xor_sync(0xffffffffu, sum, o);
    float aw_lane = e / sum;

    const int wls[4]    = {64, 32, 16, 8};
    const int hls[4]    = {64, 32, 16, 8};
    const int starts[4] = {0, 4096, 5120, 5376};

    const float* rp = refp + ((size_t)bq * Ll) * 2;
    float acc = 0.f;

    #pragma unroll
    for (int l = 0; l < Ll; l++) {
        int wl = wls[l], hl = hls[l], st = starts[l];
        float rx = rp[l*2 + 0];
        float ry = rp[l*2 + 1];
        #pragma unroll
        for (int p = 0; p < Pp; p++) {
            int n = (h*Ll + l)*Pp + p;
            float ox = off[(size_t)bq*256 + n*2 + 0];
            float oy = off[(size_t)bq*256 + n*2 + 1];
            float x = (rx + ox / (float)wl) * (float)wl - 0.5f;
            float y = (ry + oy / (float)hl) * (float)hl - 0.5f;
            float x0f = floorf(x), y0f = floorf(y);
            float lx = x - x0f, ly = y - y0f;
            int x0 = (int)x0f, y0 = (int)y0f;
            float aw = __shfl_sync(0xffffffffu, aw_lane, l*Pp + p);

            float g00 = 0.f, g01 = 0.f, g10 = 0.f, g11 = 0.f;
            if (x0   >= 0 && x0   < wl && y0   >= 0 && y0   < hl)
                g00 = value[((size_t)(b*LV + st + y0*wl + x0))*Dm + h*DH + lane];
            if (x0+1 >= 0 && x0+1 < wl && y0   >= 0 && y0   < hl)
                g01 = value[((size_t)(b*LV + st + y0*wl + x0+1))*Dm + h*DH + lane];
            if (x0   >= 0 && x0   < wl && y0+1 >= 0 && y0+1 < hl)
                g10 = value[((size_t)(b*LV + st + (y0+1)*wl + x0))*Dm + h*DH + lane];
            if (x0+1 >= 0 && x0+1 < wl && y0+1 >= 0 && y0+1 < hl)
                g11 = value[((size_t)(b*LV + st + (y0+1)*wl + x0+1))*Dm + h*DH + lane];

            float sv = g00*(1.f-lx)*(1.f-ly) + g01*lx*(1.f-ly)
                     + g10*(1.f-lx)*ly       + g11*lx*ly;
            acc += aw * sv;
        }
    }
    samp[(size_t)bq*Dm + h*DH + lane] = acc;
}

// ---------------- launch ----------------
extern "C" void kernel_launch(void* const* d_in, const int* in_sizes, int n_in,
                              void* d_out, int out_size) {
    const float* tgt  = (const float*)d_in[0];
    const float* qpos = (const float*)d_in[1];
    const float* refp = (const float*)d_in[2];
    const float* src  = (const float*)d_in[3];
    const float* in_w = (const float*)d_in[4];
    const float* in_b = (const float*)d_in[5];
    const float* ow   = (const float*)d_in[6];
    const float* ob   = (const float*)d_in[7];
    const float* n2g  = (const float*)d_in[8];
    const float* n2b  = (const float*)d_in[9];
    const float* vw   = (const float*)d_in[10];
    const float* vb   = (const float*)d_in[11];
    const float* offw = (const float*)d_in[12];
    const float* offb = (const float*)d_in[13];
    const float* aww  = (const float*)d_in[14];
    const float* awb  = (const float*)d_in[15];
    const float* opw  = (const float*)d_in[16];
    const float* opb  = (const float*)d_in[17];
    const float* n1g  = (const float*)d_in[18];
    const float* n1b  = (const float*)d_in[19];
    const float* l1w  = (const float*)d_in[20];
    const float* l1b  = (const float*)d_in[21];
    const float* l2w  = (const float*)d_in[22];
    const float* l2b  = (const float*)d_in[23];
    const float* n3g  = (const float*)d_in[24];
    const float* n3b  = (const float*)d_in[25];
    float* out = (float*)d_out;

    float *p_q, *p_qk, *p_v, *p_att, *p_tmp, *p_tgt, *p_tgt2,
          *p_value, *p_off, *p_attw, *p_samp, *p_ffn;
    cudaGetSymbolAddress((void**)&p_q,    g_q);
    cudaGetSymbolAddress((void**)&p_qk,   g_qk);
    cudaGetSymbolAddress((void**)&p_v,    g_v);
    cudaGetSymbolAddress((void**)&p_att,  g_att);
    cudaGetSymbolAddress((void**)&p_tmp,  g_tmp);
    cudaGetSymbolAddress((void**)&p_tgt,  g_tgt);
    cudaGetSymbolAddress((void**)&p_tgt2, g_tgt2);
    cudaGetSymbolAddress((void**)&p_value,g_value);
    cudaGetSymbolAddress((void**)&p_off,  g_off);
    cudaGetSymbolAddress((void**)&p_attw, g_attw);
    cudaGetSymbolAddress((void**)&p_samp, g_samp);
    cudaGetSymbolAddress((void**)&p_ffn,  g_ffn);

    const int n4 = M1 * Dm / 4;

    // 1. q = tgt + query_pos
    add_kernel<<<(n4 + 255)/256, 256>>>(tgt, qpos, p_q, n4);
    // 2. [Q|K] = q @ in_w[0:512].T + b
    gemm_kernel<<<dim3(512/GBN, M1/GBM), 256>>>(p_q, in_w, in_b, p_qk, M1, 512, Dm, 0);
    // 3. V = tgt @ in_w[512:768].T + b
    gemm_kernel<<<dim3(Dm/GBN, M1/GBM), 256>>>(tgt, in_w + 512*Dm, in_b + 512, p_v, M1, Dm, Dm, 0);
    // 4. attention
    attn_kernel<<<dim3(LQ/ATQ, Bq*Hh), ATQ>>>(p_qk, p_v, p_att);
    // 5. out_proj
    gemm_kernel<<<dim3(Dm/GBN, M1/GBM), 256>>>(p_att, ow, ob, p_tmp, M1, Dm, Dm, 0);
    // 6. tgt = LN(tgt + tgt2, norm2)
    ln_kernel<<<M1, 256>>>(tgt, p_tmp, n2g, n2b, p_tgt);
    // 7. q2 = tgt + query_pos
    add_kernel<<<(n4 + 255)/256, 256>>>(p_tgt, qpos, p_q, n4);
    // 8. value = src @ value_w.T + b
    gemm_kernel<<<dim3(Dm/GBN, MV/GBM), 256>>>(src, vw, vb, p_value, MV, Dm, Dm, 0);
    // 9. off = q2 @ off_w.T + off_b
    gemm_kernel<<<dim3(256/GBN, M1/GBM), 256>>>(p_q, offw, offb, p_off, M1, 256, Dm, 0);
    // 10. attw logits
    gemm_kernel<<<dim3(128/GBN, M1/GBM), 256>>>(p_q, aww, awb, p_attw, M1, 128, Dm, 0);
    // 11. sampler
    sampler_kernel<<<M1, 256>>>(refp, p_off, p_attw, p_value, p_samp);
    // 12. outp proj
    gemm_kernel<<<dim3(Dm/GBN, M1/GBM), 256>>>(p_samp, opw, opb, p_tmp, M1, Dm, Dm, 0);
    // 13. tgt = LN(tgt + tgt2, norm1)
    ln_kernel<<<M1, 256>>>(p_tgt, p_tmp, n1g, n1b, p_tgt2);
    // 14. ffn mid = relu
    gemm_kernel<<<dim3(DFF/GBN, M1/GBM), 256>>>(p_tgt2, l1w, l1b, p_ffn, M1, DFF, Dm, 1);
    // 15. ffn out
    gemm_kernel<<<dim3(Dm/GBN, M1/GBM), 256>>>(p_ffn, l2w, l2b, p_tmp, M1, Dm, DFF, 0);
    // 16. out = LN(tgt + t2, norm3)
    ln_kernel<<<M1, 256>>>(p_tgt2, p_tmp, n3g, n3b, out);
}

// round 5
// speedup vs baseline: 1.9451x; 1.0732x over previous
#include <cuda_runtime.h>
#include <cuda_bf16.h>
#include <math.h>

// ---------------- problem constants ----------------
#define Bq   16
#define LQ   1024
#define Dm   256
#define Hh   8
#define Ll   4
#define Pp   4
#define DFF  1024
#define DH   32
#define LV   5440
#define M1   (Bq*LQ)       // 16384
#define MV   (Bq*LV)       // 87040
#define EPSV 1e-5f

typedef unsigned long long u64;

// ---------------- f32x2 packed math helpers ----------------
__device__ __forceinline__ u64 pack2(float x, float y) {
    u64 r; asm("mov.b64 %0, {%1, %2};" : "=l"(r) : "f"(x), "f"(y)); return r;
}
__device__ __forceinline__ float2 unpack2(u64 v) {
    float2 f; asm("mov.b64 {%0, %1}, %2;" : "=f"(f.x), "=f"(f.y) : "l"(v)); return f;
}
__device__ __forceinline__ void ffma2(u64& d, u64 a, u64 b) {
    asm("fma.rn.f32x2 %0, %1, %2, %0;" : "+l"(d) : "l"(a), "l"(b));
}
__device__ __forceinline__ void fmul2(u64& d, u64 a) {
    asm("mul.rn.f32x2 %0, %0, %1;" : "+l"(d) : "l"(a));
}

// ---------------- scratch (static device, no allocs) ----------------
__device__ float g_q   [M1*Dm];
__device__ float g_qk  [M1*512];
__device__ float g_v   [M1*Dm];
__device__ float g_att [M1*Dm];
__device__ float g_tmp [M1*Dm];
__device__ float g_tgt [M1*Dm];
__device__ float g_tgt2[M1*Dm];
__device__ float g_value[(size_t)MV*Dm];
__device__ float g_off [M1*256];
__device__ float g_attw[M1*128];
__device__ float g_samp[M1*Dm];
__device__ float g_ffn [M1*DFF];

// ---------------- elementwise add ----------------
__global__ void add_kernel(const float* __restrict__ a, const float* __restrict__ b,
                           float* __restrict__ c, int n4) {
    int i = blockIdx.x * blockDim.x + threadIdx.x;
    if (i < n4) {
        float4 av = ((const float4*)a)[i];
        float4 bv = ((const float4*)b)[i];
        ((float4*)c)[i] = make_float4(av.x+bv.x, av.y+bv.y, av.z+bv.z, av.w+bv.w);
    }
}

// ---------------- SGEMM (f32x2 core): C = A(MxK) @ W(NxK)^T + bias ----------------
#define GBM 128
#define GBN 64
#define GBK 16
__global__ __launch_bounds__(256) void gemm_kernel(
    const float* __restrict__ A, const float* __restrict__ W,
    const float* __restrict__ bias, float* __restrict__ C,
    int M, int N, int K, int relu)
{
    __shared__ float As[2][GBK][GBM];
    __shared__ float Ws[2][GBK][GBN];

    const int tid = threadIdx.x;
    const int tx = tid & 15;            // col group (4 cols)
    const int ty = tid >> 4;            // row group (8 rows)
    const int m0 = blockIdx.y * GBM;
    const int n0 = blockIdx.x * GBN;

    const int ar0 = tid & 127;
    const int ak0 = tid >> 7;
    const int wr  = tid & 63;
    const int wk  = tid >> 6;

    const float* Aip = A + (size_t)(m0 + ar0) * K;
    const float* Wip = W + (size_t)(n0 + wr ) * K;

    // acc2[ii][j] = (C[row 2ii], C[row 2ii+1]) at col j   (rows within 8-row microtile)
    u64 acc2[4][4];
    #pragma unroll
    for (int i = 0; i < 4; i++)
        #pragma unroll
        for (int j = 0; j < 4; j++) acc2[i][j] = 0ull;

    {
        float4 a0 = *((const float4*)Aip + ak0);
        float4 a1 = *((const float4*)Aip + ak0 + 2);
        float4 w0 = *((const float4*)Wip + wk);
        As[0][ak0*4+0][ar0] = a0.x; As[0][ak0*4+1][ar0] = a0.y;
        As[0][ak0*4+2][ar0] = a0.z; As[0][ak0*4+3][ar0] = a0.w;
        As[0][(ak0+2)*4+0][ar0] = a1.x; As[0][(ak0+2)*4+1][ar0] = a1.y;
        As[0][(ak0+2)*4+2][ar0] = a1.z; As[0][(ak0+2)*4+3][ar0] = a1.w;
        Ws[0][wk*4+0][wr] = w0.x; Ws[0][wk*4+1][wr] = w0.y;
        Ws[0][wk*4+2][wr] = w0.z; Ws[0][wk*4+3][wr] = w0.w;
    }
    __syncthreads();

    int buf = 0;
    for (int kt = GBK; kt <= K; kt += GBK) {
        float4 pa0, pa1, pw0;
        const bool more = (kt < K);
        if (more) {
            pa0 = *((const float4*)(Aip + kt) + ak0);
            pa1 = *((const float4*)(Aip + kt) + ak0 + 2);
            pw0 = *((const float4*)(Wip + kt) + wk);
        }

        #pragma unroll
        for (int k = 0; k < GBK; k++) {
            const u64* a2 = (const u64*)&As[buf][k][ty*8];   // 4 row-pairs
            u64 ar[4] = {a2[0], a2[1], a2[2], a2[3]};
            float4 b  = *(const float4*)&Ws[buf][k][tx*4];
            u64 bb[4] = {pack2(b.x,b.x), pack2(b.y,b.y), pack2(b.z,b.z), pack2(b.w,b.w)};
            #pragma unroll
            for (int ii = 0; ii < 4; ii++)
                #pragma unroll
                for (int j = 0; j < 4; j++)
                    ffma2(acc2[ii][j], ar[ii], bb[j]);
        }

        if (more) {
            int nb = buf ^ 1;
            As[nb][ak0*4+0][ar0] = pa0.x; As[nb][ak0*4+1][ar0] = pa0.y;
            As[nb][ak0*4+2][ar0] = pa0.z; As[nb][ak0*4+3][ar0] = pa0.w;
            As[nb][(ak0+2)*4+0][ar0] = pa1.x; As[nb][(ak0+2)*4+1][ar0] = pa1.y;
            As[nb][(ak0+2)*4+2][ar0] = pa1.z; As[nb][(ak0+2)*4+3][ar0] = pa1.w;
            Ws[nb][wk*4+0][wr] = pw0.x; Ws[nb][wk*4+1][wr] = pw0.y;
            Ws[nb][wk*4+2][wr] = pw0.z; Ws[nb][wk*4+3][wr] = pw0.w;
            __syncthreads();
            buf = nb;
        }
    }

    const int n = n0 + tx*4;
    float4 b4 = *(const float4*)(bias + n);
    #pragma unroll
    for (int ii = 0; ii < 4; ii++) {
        float2 p0 = unpack2(acc2[ii][0]);
        float2 p1 = unpack2(acc2[ii][1]);
        float2 p2 = unpack2(acc2[ii][2]);
        float2 p3 = unpack2(acc2[ii][3]);
        float4 c0 = make_float4(p0.x + b4.x, p1.x + b4.y, p2.x + b4.z, p3.x + b4.w);
        float4 c1 = make_float4(p0.y + b4.x, p1.y + b4.y, p2.y + b4.z, p3.y + b4.w);
        if (relu) {
            c0.x = fmaxf(c0.x, 0.f); c0.y = fmaxf(c0.y, 0.f);
            c0.z = fmaxf(c0.z, 0.f); c0.w = fmaxf(c0.w, 0.f);
            c1.x = fmaxf(c1.x, 0.f); c1.y = fmaxf(c1.y, 0.f);
            c1.z = fmaxf(c1.z, 0.f); c1.w = fmaxf(c1.w, 0.f);
        }
        int m = m0 + ty*8 + ii*2;
        *(float4*)(C + (size_t)m     * N + n) = c0;
        *(float4*)(C + (size_t)(m+1) * N + n) = c1;
    }
}

// ---------------- flash attention (f32x2 core) ----------------
#define ATQ 128
#define KC  32
__global__ __launch_bounds__(ATQ) void attn_kernel(
    const float* __restrict__ QK, const float* __restrict__ V, float* __restrict__ O)
{
    __shared__ float Ks[KC][32];
    __shared__ float Vs[KC][32];
    __shared__ float Ss[ATQ][KC + 1];
    const int t = threadIdx.x;
    const int bh = blockIdx.y, b = bh >> 3, h = bh & 7;
    const int q = blockIdx.x * ATQ + t;

    const float4* qp = (const float4*)(QK + ((size_t)(b*LQ + q))*512 + h*DH);
    float4 qv[8];
    #pragma unroll
    for (int i = 0; i < 8; i++) qv[i] = qp[i];
    const u64* q2 = (const u64*)qv;       // 16 packed pairs

    u64 o2[16];
    #pragma unroll
    for (int i = 0; i < 16; i++) o2[i] = 0ull;
    float m = -1e30f, l = 0.f;
    const float scale = 0.17677669529663687f; // 1/sqrt(32)

    const int sr0 = t >> 3;
    const int sc  = t & 7;

    for (int kc = 0; kc < LQ; kc += KC) {
        #pragma unroll
        for (int ph = 0; ph < 2; ph++) {
            int row = sr0 + ph*16;
            const float4* kp = (const float4*)(QK + ((size_t)(b*LQ + kc + row))*512 + 256 + h*DH);
            const float4* vp = (const float4*)(V  + ((size_t)(b*LQ + kc + row))*Dm  + h*DH);
            *((float4*)Ks[row] + sc) = kp[sc];
            *((float4*)Vs[row] + sc) = vp[sc];
        }
        __syncthreads();

        float cmax = -1e30f;
        #pragma unroll 8
        for (int j = 0; j < KC; j++) {
            const u64* kk = (const u64*)Ks[j];
            u64 d2 = 0ull;
            #pragma unroll
            for (int i = 0; i < 16; i++) ffma2(d2, q2[i], kk[i]);
            float2 dd = unpack2(d2);
            float d = (dd.x + dd.y) * scale;
            Ss[t][j] = d;
            cmax = fmaxf(cmax, d);
        }
        float mnew = fmaxf(m, cmax);
        float corr = __expf(m - mnew);
        l *= corr;
        u64 cc = pack2(corr, corr);
        #pragma unroll
        for (int i = 0; i < 16; i++) fmul2(o2[i], cc);

        #pragma unroll 4
        for (int j = 0; j < KC; j++) {
            float p = __expf(Ss[t][j] - mnew);
            l += p;
            u64 pp = pack2(p, p);
            const u64* vv = (const u64*)Vs[j];
            #pragma unroll
            for (int i = 0; i < 16; i++) ffma2(o2[i], pp, vv[i]);
        }
        m = mnew;
        __syncthreads();
    }

    float inv = 1.f / l;
    u64 iv = pack2(inv, inv);
    u64* op = (u64*)(O + ((size_t)(b*LQ + q))*Dm + h*DH);
    #pragma unroll
    for (int i = 0; i < 16; i++) {
        fmul2(o2[i], iv);
        op[i] = o2[i];
    }
}

// ---------------- layernorm(a + b) * g + beta ----------------
__global__ __launch_bounds__(256) void ln_kernel(
    const float* __restrict__ a, const float* __restrict__ b,
    const float* __restrict__ g, const float* __restrict__ be,
    float* __restrict__ out)
{
    __shared__ float red[8];
    int row = blockIdx.x, t = threadIdx.x;
    float x = a[(size_t)row*Dm + t] + b[(size_t)row*Dm + t];

    float s = x;
    #pragma unroll
    for (int o = 16; o; o >>= 1) s += __shfl_xor_sync(0xffffffffu, s, o);
    if ((t & 31) == 0) red[t >> 5] = s;
    __syncthreads();
    float tot = 0.f;
    #pragma unroll
    for (int i = 0; i < 8; i++) tot += red[i];
    float mean = tot * (1.f / Dm);
    float d0 = x - mean;
    __syncthreads();

    float sq = d0 * d0;
    #pragma unroll
    for (int o = 16; o; o >>= 1) sq += __shfl_xor_sync(0xffffffffu, sq, o);
    if ((t & 31) == 0) red[t >> 5] = sq;
    __syncthreads();
    float tot2 = 0.f;
    #pragma unroll
    for (int i = 0; i < 8; i++) tot2 += red[i];
    float var = tot2 * (1.f / Dm);

    out[(size_t)row*Dm + t] = d0 * rsqrtf(var + EPSV) * g[t] + be[t];
}

// ---------------- deformable sampler (attw softmax fused) ----------------
__global__ __launch_bounds__(256) void sampler_kernel(
    const float* __restrict__ refp,
    const float* __restrict__ off,
    const float* __restrict__ attw,
    const float* __restrict__ value,
    float* __restrict__ samp)
{
    int bq = blockIdx.x;
    int b = bq >> 10;
    int t = threadIdx.x;
    int h = t >> 5, lane = t & 31;

    float logit = (lane < 16) ? attw[(size_t)bq*128 + h*16 + lane] : -1e30f;
    float mx = logit;
    #pragma unroll
    for (int o = 16; o; o >>= 1) mx = fmaxf(mx, __shfl_xor_sync(0xffffffffu, mx, o));
    float e = (lane < 16) ? __expf(logit - mx) : 0.f;
    float sum = e;
    #pragma unroll
    for (int o = 16; o; o >>= 1) sum += __shfl_xor_sync(0xffffffffu, sum, o);
    float aw_lane = e / sum;

    const int wls[4]    = {64, 32, 16, 8};
    const int hls[4]    = {64, 32, 16, 8};
    const int starts[4] = {0, 4096, 5120, 5376};

    const float* rp = refp + ((size_t)bq * Ll) * 2;
    float acc = 0.f;

    #pragma unroll
    for (int l = 0; l < Ll; l++) {
        int wl = wls[l], hl = hls[l], st = starts[l];
        float rx = rp[l*2 + 0];
        float ry = rp[l*2 + 1];
        #pragma unroll
        for (int p = 0; p < Pp; p++) {
            int n = (h*Ll + l)*Pp + p;
            float ox = off[(size_t)bq*256 + n*2 + 0];
            float oy = off[(size_t)bq*256 + n*2 + 1];
            float x = (rx + ox / (float)wl) * (float)wl - 0.5f;
            float y = (ry + oy / (float)hl) * (float)hl - 0.5f;
            float x0f = floorf(x), y0f = floorf(y);
            float lx = x - x0f, ly = y - y0f;
            int x0 = (int)x0f, y0 = (int)y0f;
            float aw = __shfl_sync(0xffffffffu, aw_lane, l*Pp + p);

            float g00 = 0.f, g01 = 0.f, g10 = 0.f, g11 = 0.f;
            if (x0   >= 0 && x0   < wl && y0   >= 0 && y0   < hl)
                g00 = value[((size_t)(b*LV + st + y0*wl + x0))*Dm + h*DH + lane];
            if (x0+1 >= 0 && x0+1 < wl && y0   >= 0 && y0   < hl)
                g01 = value[((size_t)(b*LV + st + y0*wl + x0+1))*Dm + h*DH + lane];
            if (x0   >= 0 && x0   < wl && y0+1 >= 0 && y0+1 < hl)
                g10 = value[((size_t)(b*LV + st + (y0+1)*wl + x0))*Dm + h*DH + lane];
            if (x0+1 >= 0 && x0+1 < wl && y0+1 >= 0 && y0+1 < hl)
                g11 = value[((size_t)(b*LV + st + (y0+1)*wl + x0+1))*Dm + h*DH + lane];

            float sv = g00*(1.f-lx)*(1.f-ly) + g01*lx*(1.f-ly)
                     + g10*(1.f-lx)*ly       + g11*lx*ly;
            acc += aw * sv;
        }
    }
    samp[(size_t)bq*Dm + h*DH + lane] = acc;
}

// ---------------- launch ----------------
extern "C" void kernel_launch(void* const* d_in, const int* in_sizes, int n_in,
                              void* d_out, int out_size) {
    const float* tgt  = (const float*)d_in[0];
    const float* qpos = (const float*)d_in[1];
    const float* refp = (const float*)d_in[2];
    const float* src  = (const float*)d_in[3];
    const float* in_w = (const float*)d_in[4];
    const float* in_b = (const float*)d_in[5];
    const float* ow   = (const float*)d_in[6];
    const float* ob   = (const float*)d_in[7];
    const float* n2g  = (const float*)d_in[8];
    const float* n2b  = (const float*)d_in[9];
    const float* vw   = (const float*)d_in[10];
    const float* vb   = (const float*)d_in[11];
    const float* offw = (const float*)d_in[12];
    const float* offb = (const float*)d_in[13];
    const float* aww  = (const float*)d_in[14];
    const float* awb  = (const float*)d_in[15];
    const float* opw  = (const float*)d_in[16];
    const float* opb  = (const float*)d_in[17];
    const float* n1g  = (const float*)d_in[18];
    const float* n1b  = (const float*)d_in[19];
    const float* l1w  = (const float*)d_in[20];
    const float* l1b  = (const float*)d_in[21];
    const float* l2w  = (const float*)d_in[22];
    const float* l2b  = (const float*)d_in[23];
    const float* n3g  = (const float*)d_in[24];
    const float* n3b  = (const float*)d_in[25];
    float* out = (float*)d_out;

    float *p_q, *p_qk, *p_v, *p_att, *p_tmp, *p_tgt, *p_tgt2,
          *p_value, *p_off, *p_attw, *p_samp, *p_ffn;
    cudaGetSymbolAddress((void**)&p_q,    g_q);
    cudaGetSymbolAddress((void**)&p_qk,   g_qk);
    cudaGetSymbolAddress((void**)&p_v,    g_v);
    cudaGetSymbolAddress((void**)&p_att,  g_att);
    cudaGetSymbolAddress((void**)&p_tmp,  g_tmp);
    cudaGetSymbolAddress((void**)&p_tgt,  g_tgt);
    cudaGetSymbolAddress((void**)&p_tgt2, g_tgt2);
    cudaGetSymbolAddress((void**)&p_value,g_value);
    cudaGetSymbolAddress((void**)&p_off,  g_off);
    cudaGetSymbolAddress((void**)&p_attw, g_attw);
    cudaGetSymbolAddress((void**)&p_samp, g_samp);
    cudaGetSymbolAddress((void**)&p_ffn,  g_ffn);

    const int n4 = M1 * Dm / 4;

    add_kernel<<<(n4 + 255)/256, 256>>>(tgt, qpos, p_q, n4);
    gemm_kernel<<<dim3(512/GBN, M1/GBM), 256>>>(p_q, in_w, in_b, p_qk, M1, 512, Dm, 0);
    gemm_kernel<<<dim3(Dm/GBN, M1/GBM), 256>>>(tgt, in_w + 512*Dm, in_b + 512, p_v, M1, Dm, Dm, 0);
    attn_kernel<<<dim3(LQ/ATQ, Bq*Hh), ATQ>>>(p_qk, p_v, p_att);
    gemm_kernel<<<dim3(Dm/GBN, M1/GBM), 256>>>(p_att, ow, ob, p_tmp, M1, Dm, Dm, 0);
    ln_kernel<<<M1, 256>>>(tgt, p_tmp, n2g, n2b, p_tgt);
    add_kernel<<<(n4 + 255)/256, 256>>>(p_tgt, qpos, p_q, n4);
    gemm_kernel<<<dim3(Dm/GBN, MV/GBM), 256>>>(src, vw, vb, p_value, MV, Dm, Dm, 0);
    gemm_kernel<<<dim3(256/GBN, M1/GBM), 256>>>(p_q, offw, offb, p_off, M1, 256, Dm, 0);
    gemm_kernel<<<dim3(128/GBN, M1/GBM), 256>>>(p_q, aww, awb, p_attw, M1, 128, Dm, 0);
    sampler_kernel<<<M1, 256>>>(refp, p_off, p_attw, p_value, p_samp);
    gemm_kernel<<<dim3(Dm/GBN, M1/GBM), 256>>>(p_samp, opw, opb, p_tmp, M1, Dm, Dm, 0);
    ln_kernel<<<M1, 256>>>(p_tgt, p_tmp, n1g, n1b, p_tgt2);
    gemm_kernel<<<dim3(DFF/GBN, M1/GBM), 256>>>(p_tgt2, l1w, l1b, p_ffn, M1, DFF, Dm, 1);
    gemm_kernel<<<dim3(Dm/GBN, M1/GBM), 256>>>(p_ffn, l2w, l2b, p_tmp, M1, Dm, DFF, 0);
    ln_kernel<<<M1, 256>>>(p_tgt2, p_tmp, n3g, n3b, out);
}

// round 8
// speedup vs baseline: 2.7379x; 1.4076x over previous
#include <cuda_runtime.h>
#include <cuda_bf16.h>
#include <math.h>
#include <stdint.h>

// ---------------- problem constants ----------------
#define Bq   16
#define LQ   1024
#define Dm   256
#define Hh   8
#define Ll   4
#define Pp   4
#define DFF  1024
#define DH   32
#define LV   5440
#define M1   (Bq*LQ)       // 16384
#define MV   (Bq*LV)       // 87040
#define EPSV 1e-5f

typedef unsigned long long u64;
typedef uint32_t u32;

// ---------------- f32x2 helpers (attention) ----------------
__device__ __forceinline__ u64 pack2(float x, float y) {
    u64 r; asm("mov.b64 %0, {%1, %2};" : "=l"(r) : "f"(x), "f"(y)); return r;
}
__device__ __forceinline__ float2 unpack2(u64 v) {
    float2 f; asm("mov.b64 {%0, %1}, %2;" : "=f"(f.x), "=f"(f.y) : "l"(v)); return f;
}
__device__ __forceinline__ void ffma2(u64& d, u64 a, u64 b) {
    asm("fma.rn.f32x2 %0, %1, %2, %0;" : "+l"(d) : "l"(a), "l"(b));
}
__device__ __forceinline__ void fmul2(u64& d, u64 a) {
    asm("mul.rn.f32x2 %0, %0, %1;" : "+l"(d) : "l"(a));
}

// ---------------- HMMA helper (portable sm_80+ path) ----------------
__device__ __forceinline__ void mma16816(float* c, const u32* a, const u32* b) {
    asm volatile(
        "mma.sync.aligned.m16n8k16.row.col.f32.bf16.bf16.f32 "
        "{%0,%1,%2,%3}, {%4,%5,%6,%7}, {%8,%9}, {%0,%1,%2,%3};"
        : "+f"(c[0]), "+f"(c[1]), "+f"(c[2]), "+f"(c[3])
        : "r"(a[0]), "r"(a[1]), "r"(a[2]), "r"(a[3]), "r"(b[0]), "r"(b[1]));
}

// ---------------- scratch (static device, no allocs) ----------------
__device__ float g_qk  [M1*512];
__device__ float g_v   [M1*Dm];
__device__ float g_att [M1*Dm];
__device__ float g_tmp [M1*Dm];
__device__ float g_tgt [M1*Dm];
__device__ float g_tgt2[M1*Dm];
__device__ float g_value[(size_t)MV*Dm];
__device__ float g_off [M1*256];
__device__ float g_attw[M1*128];
__device__ float g_samp[M1*Dm];
__device__ float g_ffn [M1*DFF];

#define AMAX ((size_t)MV*Dm)
__device__ __nv_bfloat16 g_ahi[AMAX];
__device__ __nv_bfloat16 g_alo[AMAX];
#define WTOT 1015808
__device__ __nv_bfloat16 g_whi[WTOT];
__device__ __nv_bfloat16 g_wlo[WTOT];

#define WO_IN   0
#define WO_INV  131072
#define WO_OW   196608
#define WO_VW   262144
#define WO_OFF  327680
#define WO_AW   393216
#define WO_OP   425984
#define WO_L1   491520
#define WO_L2   753664

// ---------------- fp32 -> (bf16 hi, bf16 lo) split ----------------
__device__ __forceinline__ void split1(float x, __nv_bfloat16& h, __nv_bfloat16& l) {
    h = __float2bfloat16(x);
    l = __float2bfloat16(x - __bfloat162float(h));
}
__global__ void split_kernel(const float* __restrict__ x,
                             __nv_bfloat16* __restrict__ hi,
                             __nv_bfloat16* __restrict__ lo, int n4) {
    int i = blockIdx.x * blockDim.x + threadIdx.x;
    if (i < n4) {
        float4 v = ((const float4*)x)[i];
        __nv_bfloat16 h0,h1,h2,h3,l0,l1,l2,l3;
        split1(v.x,h0,l0); split1(v.y,h1,l1); split1(v.z,h2,l2); split1(v.w,h3,l3);
        ((__nv_bfloat162*)hi)[2*i]   = __nv_bfloat162(h0,h1);
        ((__nv_bfloat162*)hi)[2*i+1] = __nv_bfloat162(h2,h3);
        ((__nv_bfloat162*)lo)[2*i]   = __nv_bfloat162(l0,l1);
        ((__nv_bfloat162*)lo)[2*i+1] = __nv_bfloat162(l2,l3);
    }
}
__global__ void add_split_kernel(const float* __restrict__ a, const float* __restrict__ b,
                                 __nv_bfloat16* __restrict__ hi,
                                 __nv_bfloat16* __restrict__ lo, int n4) {
    int i = blockIdx.x * blockDim.x + threadIdx.x;
    if (i < n4) {
        float4 av = ((const float4*)a)[i];
        float4 bv = ((const float4*)b)[i];
        float4 v = make_float4(av.x+bv.x, av.y+bv.y, av.z+bv.z, av.w+bv.w);
        __nv_bfloat16 h0,h1,h2,h3,l0,l1,l2,l3;
        split1(v.x,h0,l0); split1(v.y,h1,l1); split1(v.z,h2,l2); split1(v.w,h3,l3);
        ((__nv_bfloat162*)hi)[2*i]   = __nv_bfloat162(h0,h1);
        ((__nv_bfloat162*)hi)[2*i+1] = __nv_bfloat162(h2,h3);
        ((__nv_bfloat162*)lo)[2*i]   = __nv_bfloat162(l0,l1);
        ((__nv_bfloat162*)lo)[2*i+1] = __nv_bfloat162(l2,l3);
    }
}

// ---------------- split-bf16 HMMA GEMM ----------------
// C[M,N] = (Ahi+Alo)(M,K) @ (Whi+Wlo)(N,K)^T + bias; grid=(N/64, M/128), 256 thr.
// smem tiles padded to stride 40 bf16 (80 B) -> conflict-free fragment loads.
#define KCH 32
#define SSTR 40
__global__ __launch_bounds__(256) void mma_gemm(
    const __nv_bfloat16* __restrict__ Ahi, const __nv_bfloat16* __restrict__ Alo,
    const __nv_bfloat16* __restrict__ Whi, const __nv_bfloat16* __restrict__ Wlo,
    const float* __restrict__ bias, float* __restrict__ C,
    int K, int N, int relu)
{
    __shared__ __nv_bfloat16 sAh[128*SSTR], sAl[128*SSTR];
    __shared__ __nv_bfloat16 sBh[64*SSTR],  sBl[64*SSTR];

    const int tid  = threadIdx.x;
    const int lane = tid & 31, wid = tid >> 5;
    const int wm = wid >> 1, wn = wid & 1;         // 4 x 2 warp grid
    const int m0 = blockIdx.y * 128, n0 = blockIdx.x * 64;
    const int r = lane >> 2, q = (lane & 3) * 2;

    float acc[2][4][4];
    #pragma unroll
    for (int mi = 0; mi < 2; mi++)
        #pragma unroll
        for (int ni = 0; ni < 4; ni++)
            #pragma unroll
            for (int c = 0; c < 4; c++) acc[mi][ni][c] = 0.f;

    for (int kc = 0; kc < K; kc += KCH) {
        // ---- stage A (128x32 hi+lo) ----
        #pragma unroll
        for (int it = 0; it < 2; it++) {
            int i = tid + it * 256;
            int row = i >> 2, c8 = i & 3;
            size_t gof = (size_t)(m0 + row) * K + kc + c8 * 8;
            int so = row * SSTR + c8 * 8;
            *(uint4*)&sAh[so] = *(const uint4*)(Ahi + gof);
            *(uint4*)&sAl[so] = *(const uint4*)(Alo + gof);
        }
        // ---- stage B (64x32 hi+lo) ----
        {
            int row = tid >> 2, c8 = tid & 3;
            size_t gof = (size_t)(n0 + row) * K + kc + c8 * 8;
            int so = row * SSTR + c8 * 8;
            *(uint4*)&sBh[so] = *(const uint4*)(Whi + gof);
            *(uint4*)&sBl[so] = *(const uint4*)(Wlo + gof);
        }
        __syncthreads();

        #pragma unroll
        for (int ks = 0; ks < KCH; ks += 16) {
            u32 ah[2][4], al[2][4];
            #pragma unroll
            for (int mi = 0; mi < 2; mi++) {
                int base = wm*32 + mi*16;
                int o00 = (base + r    ) * SSTR + ks + q;
                int o10 = (base + r + 8) * SSTR + ks + q;
                ah[mi][0] = *(const u32*)&sAh[o00];
                ah[mi][1] = *(const u32*)&sAh[o10];
                ah[mi][2] = *(const u32*)&sAh[o00 + 8];
                ah[mi][3] = *(const u32*)&sAh[o10 + 8];
                al[mi][0] = *(const u32*)&sAl[o00];
                al[mi][1] = *(const u32*)&sAl[o10];
                al[mi][2] = *(const u32*)&sAl[o00 + 8];
                al[mi][3] = *(const u32*)&sAl[o10 + 8];
            }
            u32 bh[4][2], bl[4][2];
            #pragma unroll
            for (int ni = 0; ni < 4; ni++) {
                int base = wn*32 + ni*8;
                int o = (base + r) * SSTR + ks + q;
                bh[ni][0] = *(const u32*)&sBh[o];
                bh[ni][1] = *(const u32*)&sBh[o + 8];
                bl[ni][0] = *(const u32*)&sBl[o];
                bl[ni][1] = *(const u32*)&sBl[o + 8];
            }
            #pragma unroll
            for (int mi = 0; mi < 2; mi++)
                #pragma unroll
                for (int ni = 0; ni < 4; ni++) {
                    mma16816(acc[mi][ni], ah[mi], bh[ni]);
                    mma16816(acc[mi][ni], ah[mi], bl[ni]);
                    mma16816(acc[mi][ni], al[mi], bh[ni]);
                }
        }
        __syncthreads();
    }

    // ---- epilogue: bias + relu, direct float2 stores ----
    #pragma unroll
    for (int mi = 0; mi < 2; mi++) {
        int row0 = m0 + wm*32 + mi*16 + r;
        #pragma unroll
        for (int ni = 0; ni < 4; ni++) {
            int col = n0 + wn*32 + ni*8 + q;
            float2 bv = *(const float2*)(bias + col);
            float2 v0 = make_float2(acc[mi][ni][0] + bv.x, acc[mi][ni][1] + bv.y);
            float2 v1 = make_float2(acc[mi][ni][2] + bv.x, acc[mi][ni][3] + bv.y);
            if (relu) {
                v0.x = fmaxf(v0.x, 0.f); v0.y = fmaxf(v0.y, 0.f);
                v1.x = fmaxf(v1.x, 0.f); v1.y = fmaxf(v1.y, 0.f);
            }
            *(float2*)(C + (size_t)row0     * N + col) = v0;
            *(float2*)(C + (size_t)(row0+8) * N + col) = v1;
        }
    }
}

// ---------------- flash attention (f32x2 core) ----------------
#define ATQ 128
#define KC  32
__global__ __launch_bounds__(ATQ) void attn_kernel(
    const float* __restrict__ QK, const float* __restrict__ V, float* __restrict__ O)
{
    __shared__ float Ks[KC][32];
    __shared__ float Vs[KC][32];
    __shared__ float Ss[ATQ][KC + 1];
    const int t = threadIdx.x;
    const int bh = blockIdx.y, b = bh >> 3, h = bh & 7;
    const int q = blockIdx.x * ATQ + t;

    const float4* qp = (const float4*)(QK + ((size_t)(b*LQ + q))*512 + h*DH);
    float4 qv[8];
    #pragma unroll
    for (int i = 0; i < 8; i++) qv[i] = qp[i];
    const u64* q2 = (const u64*)qv;

    u64 o2[16];
    #pragma unroll
    for (int i = 0; i < 16; i++) o2[i] = 0ull;
    float m = -1e30f, l = 0.f;
    const float scale = 0.17677669529663687f;

    const int sr0 = t >> 3;
    const int sc  = t & 7;

    for (int kc = 0; kc < LQ; kc += KC) {
        #pragma unroll
        for (int ph = 0; ph < 2; ph++) {
            int row = sr0 + ph*16;
            const float4* kp = (const float4*)(QK + ((size_t)(b*LQ + kc + row))*512 + 256 + h*DH);
            const float4* vp = (const float4*)(V  + ((size_t)(b*LQ + kc + row))*Dm  + h*DH);
            *((float4*)Ks[row] + sc) = kp[sc];
            *((float4*)Vs[row] + sc) = vp[sc];
        }
        __syncthreads();

        float cmax = -1e30f;
        #pragma unroll 8
        for (int j = 0; j < KC; j++) {
            const u64* kk = (const u64*)Ks[j];
            u64 d2 = 0ull;
            #pragma unroll
            for (int i = 0; i < 16; i++) ffma2(d2, q2[i], kk[i]);
            float2 dd = unpack2(d2);
            float d = (dd.x + dd.y) * scale;
            Ss[t][j] = d;
            cmax = fmaxf(cmax, d);
        }
        float mnew = fmaxf(m, cmax);
        float corr = __expf(m - mnew);
        l *= corr;
        u64 cc = pack2(corr, corr);
        #pragma unroll
        for (int i = 0; i < 16; i++) fmul2(o2[i], cc);

        #pragma unroll 4
        for (int j = 0; j < KC; j++) {
            float p = __expf(Ss[t][j] - mnew);
            l += p;
            u64 pp = pack2(p, p);
            const u64* vv = (const u64*)Vs[j];
            #pragma unroll
            for (int i = 0; i < 16; i++) ffma2(o2[i], pp, vv[i]);
        }
        m = mnew;
        __syncthreads();
    }

    float inv = 1.f / l;
    u64 iv = pack2(inv, inv);
    u64* op = (u64*)(O + ((size_t)(b*LQ + q))*Dm + h*DH);
    #pragma unroll
    for (int i = 0; i < 16; i++) {
        fmul2(o2[i], iv);
        op[i] = o2[i];
    }
}

// ---------------- layernorm(a + b) * g + beta ----------------
__global__ __launch_bounds__(256) void ln_kernel(
    const float* __restrict__ a, const float* __restrict__ b,
    const float* __restrict__ g, const float* __restrict__ be,
    float* __restrict__ out)
{
    __shared__ float red[8];
    int row = blockIdx.x, t = threadIdx.x;
    float x = a[(size_t)row*Dm + t] + b[(size_t)row*Dm + t];

    float s = x;
    #pragma unroll
    for (int o = 16; o; o >>= 1) s += __shfl_xor_sync(0xffffffffu, s, o);
    if ((t & 31) == 0) red[t >> 5] = s;
    __syncthreads();
    float tot = 0.f;
    #pragma unroll
    for (int i = 0; i < 8; i++) tot += red[i];
    float mean = tot * (1.f / Dm);
    float d0 = x - mean;
    __syncthreads();

    float sq = d0 * d0;
    #pragma unroll
    for (int o = 16; o; o >>= 1) sq += __shfl_xor_sync(0xffffffffu, sq, o);
    if ((t & 31) == 0) red[t >> 5] = sq;
    __syncthreads();
    float tot2 = 0.f;
    #pragma unroll
    for (int i = 0; i < 8; i++) tot2 += red[i];
    float var = tot2 * (1.f / Dm);

    out[(size_t)row*Dm + t] = d0 * rsqrtf(var + EPSV) * g[t] + be[t];
}

// ---------------- deformable sampler (attw softmax fused) ----------------
__global__ __launch_bounds__(256) void sampler_kernel(
    const float* __restrict__ refp,
    const float* __restrict__ off,
    const float* __restrict__ attw,
    const float* __restrict__ value,
    float* __restrict__ samp)
{
    int bq = blockIdx.x;
    int b = bq >> 10;
    int t = threadIdx.x;
    int h = t >> 5, lane = t & 31;

    float logit = (lane < 16) ? attw[(size_t)bq*128 + h*16 + lane] : -1e30f;
    float mx = logit;
    #pragma unroll
    for (int o = 16; o; o >>= 1) mx = fmaxf(mx, __shfl_xor_sync(0xffffffffu, mx, o));
    float e = (lane < 16) ? __expf(logit - mx) : 0.f;
    float sum = e;
    #pragma unroll
    for (int o = 16; o; o >>= 1) sum += __shfl_xor_sync(0xffffffffu, sum, o);
    float aw_lane = e / sum;

    const int wls[4]    = {64, 32, 16, 8};
    const int hls[4]    = {64, 32, 16, 8};
    const int starts[4] = {0, 4096, 5120, 5376};

    const float* rp = refp + ((size_t)bq * Ll) * 2;
    float acc = 0.f;

    #pragma unroll
    for (int l = 0; l < Ll; l++) {
        int wl = wls[l], hl = hls[l], st = starts[l];
        float rx = rp[l*2 + 0];
        float ry = rp[l*2 + 1];
        #pragma unroll
        for (int p = 0; p < Pp; p++) {
            int n = (h*Ll + l)*Pp + p;
            float ox = off[(size_t)bq*256 + n*2 + 0];
            float oy = off[(size_t)bq*256 + n*2 + 1];
            float x = (rx + ox / (float)wl) * (float)wl - 0.5f;
            float y = (ry + oy / (float)hl) * (float)hl - 0.5f;
            float x0f = floorf(x), y0f = floorf(y);
            float lx = x - x0f, ly = y - y0f;
            int x0 = (int)x0f, y0 = (int)y0f;
            float aw = __shfl_sync(0xffffffffu, aw_lane, l*Pp + p);

            float g00 = 0.f, g01 = 0.f, g10 = 0.f, g11 = 0.f;
            if (x0   >= 0 && x0   < wl && y0   >= 0 && y0   < hl)
                g00 = value[((size_t)(b*LV + st + y0*wl + x0))*Dm + h*DH + lane];
            if (x0+1 >= 0 && x0+1 < wl && y0   >= 0 && y0   < hl)
                g01 = value[((size_t)(b*LV + st + y0*wl + x0+1))*Dm + h*DH + lane];
            if (x0   >= 0 && x0   < wl && y0+1 >= 0 && y0+1 < hl)
                g10 = value[((size_t)(b*LV + st + (y0+1)*wl + x0))*Dm + h*DH + lane];
            if (x0+1 >= 0 && x0+1 < wl && y0+1 >= 0 && y0+1 < hl)
                g11 = value[((size_t)(b*LV + st + (y0+1)*wl + x0+1))*Dm + h*DH + lane];

            float sv = g00*(1.f-lx)*(1.f-ly) + g01*lx*(1.f-ly)
                     + g10*(1.f-lx)*ly       + g11*lx*ly;
            acc += aw * sv;
        }
    }
    samp[(size_t)bq*Dm + h*DH + lane] = acc;
}

// ---------------- launch ----------------
extern "C" void kernel_launch(void* const* d_in, const int* in_sizes, int n_in,
                              void* d_out, int out_size) {
    const float* tgt  = (const float*)d_in[0];
    const float* qpos = (const float*)d_in[1];
    const float* refp = (const float*)d_in[2];
    const float* src  = (const float*)d_in[3];
    const float* in_w = (const float*)d_in[4];
    const float* in_b = (const float*)d_in[5];
    const float* ow   = (const float*)d_in[6];
    const float* ob   = (const float*)d_in[7];
    const float* n2g  = (const float*)d_in[8];
    const float* n2b  = (const float*)d_in[9];
    const float* vw   = (const float*)d_in[10];
    const float* vb   = (const float*)d_in[11];
    const float* offw = (const float*)d_in[12];
    const float* offb = (const float*)d_in[13];
    const float* aww  = (const float*)d_in[14];
    const float* awb  = (const float*)d_in[15];
    const float* opw  = (const float*)d_in[16];
    const float* opb  = (const float*)d_in[17];
    const float* n1g  = (const float*)d_in[18];
    const float* n1b  = (const float*)d_in[19];
    const float* l1w  = (const float*)d_in[20];
    const float* l1b  = (const float*)d_in[21];
    const float* l2w  = (const float*)d_in[22];
    const float* l2b  = (const float*)d_in[23];
    const float* n3g  = (const float*)d_in[24];
    const float* n3b  = (const float*)d_in[25];
    float* out = (float*)d_out;

    float *p_qk, *p_v, *p_att, *p_tmp, *p_tgt, *p_tgt2,
          *p_value, *p_off, *p_attw, *p_samp, *p_ffn;
    __nv_bfloat16 *p_ahi, *p_alo, *p_whi, *p_wlo;
    cudaGetSymbolAddress((void**)&p_qk,   g_qk);
    cudaGetSymbolAddress((void**)&p_v,    g_v);
    cudaGetSymbolAddress((void**)&p_att,  g_att);
    cudaGetSymbolAddress((void**)&p_tmp,  g_tmp);
    cudaGetSymbolAddress((void**)&p_tgt,  g_tgt);
    cudaGetSymbolAddress((void**)&p_tgt2, g_tgt2);
    cudaGetSymbolAddress((void**)&p_value,g_value);
    cudaGetSymbolAddress((void**)&p_off,  g_off);
    cudaGetSymbolAddress((void**)&p_attw, g_attw);
    cudaGetSymbolAddress((void**)&p_samp, g_samp);
    cudaGetSymbolAddress((void**)&p_ffn,  g_ffn);
    cudaGetSymbolAddress((void**)&p_ahi,  g_ahi);
    cudaGetSymbolAddress((void**)&p_alo,  g_alo);
    cudaGetSymbolAddress((void**)&p_whi,  g_whi);
    cudaGetSymbolAddress((void**)&p_wlo,  g_wlo);

    const int n4 = M1 * Dm / 4;

    // ---- weight splits ----
    #define SPL(src_, off_, n_) split_kernel<<<((n_)/4 + 255)/256, 256>>>(src_, p_whi + (off_), p_wlo + (off_), (n_)/4)
    SPL(in_w, WO_IN,  768*256);
    SPL(ow,   WO_OW,  65536);
    SPL(vw,   WO_VW,  65536);
    SPL(offw, WO_OFF, 65536);
    SPL(aww,  WO_AW,  32768);
    SPL(opw,  WO_OP,  65536);
    SPL(l1w,  WO_L1,  262144);
    SPL(l2w,  WO_L2,  262144);
    #undef SPL

    // 1. q = tgt + qpos -> bf16 split
    add_split_kernel<<<(n4 + 255)/256, 256>>>(tgt, qpos, p_ahi, p_alo, n4);
    // 2. [Q|K] = q @ in_w[0:512].T + b
    mma_gemm<<<dim3(8, M1/128), 256>>>(p_ahi, p_alo, p_whi + WO_IN, p_wlo + WO_IN, in_b, p_qk, 256, 512, 0);
    // 3. V = tgt @ in_w[512:768].T + b
    split_kernel<<<(n4 + 255)/256, 256>>>(tgt, p_ahi, p_alo, n4);
    mma_gemm<<<dim3(4, M1/128), 256>>>(p_ahi, p_alo, p_whi + WO_INV, p_wlo + WO_INV, in_b + 512, p_v, 256, 256, 0);
    // 4. attention
    attn_kernel<<<dim3(LQ/ATQ, Bq*Hh), ATQ>>>(p_qk, p_v, p_att);
    // 5. out_proj
    split_kernel<<<(n4 + 255)/256, 256>>>(p_att, p_ahi, p_alo, n4);
    mma_gemm<<<dim3(4, M1/128), 256>>>(p_ahi, p_alo, p_whi + WO_OW, p_wlo + WO_OW, ob, p_tmp, 256, 256, 0);
    // 6. tgt = LN(tgt + tgt2, norm2)
    ln_kernel<<<M1, 256>>>(tgt, p_tmp, n2g, n2b, p_tgt);
    // 7. q2 = tgt + qpos -> off + attw projections
    add_split_kernel<<<(n4 + 255)/256, 256>>>(p_tgt, qpos, p_ahi, p_alo, n4);
    mma_gemm<<<dim3(4, M1/128), 256>>>(p_ahi, p_alo, p_whi + WO_OFF, p_wlo + WO_OFF, offb, p_off, 256, 256, 0);
    mma_gemm<<<dim3(2, M1/128), 256>>>(p_ahi, p_alo, p_whi + WO_AW, p_wlo + WO_AW, awb, p_attw, 256, 128, 0);
    // 8. value = src @ value_w.T + b
    split_kernel<<<((int)(MV*(size_t)Dm/4) + 255)/256, 256>>>(src, p_ahi, p_alo, (int)(MV*(size_t)Dm/4));
    mma_gemm<<<dim3(4, MV/128), 256>>>(p_ahi, p_alo, p_whi + WO_VW, p_wlo + WO_VW, vb, p_value, 256, 256, 0);
    // 9. sampler
    sampler_kernel<<<M1, 256>>>(refp, p_off, p_attw, p_value, p_samp);
    // 10. outp proj
    split_kernel<<<(n4 + 255)/256, 256>>>(p_samp, p_ahi, p_alo, n4);
    mma_gemm<<<dim3(4, M1/128), 256>>>(p_ahi, p_alo, p_whi + WO_OP, p_wlo + WO_OP, opb, p_tmp, 256, 256, 0);
    // 11. tgt2 = LN(tgt + t, norm1)
    ln_kernel<<<M1, 256>>>(p_tgt, p_tmp, n1g, n1b, p_tgt2);
    // 12. ffn mid = relu(tgt2 @ l1w.T + b)
    split_kernel<<<(n4 + 255)/256, 256>>>(p_tgt2, p_ahi, p_alo, n4);
    mma_gemm<<<dim3(16, M1/128), 256>>>(p_ahi, p_alo, p_whi + WO_L1, p_wlo + WO_L1, l1b, p_ffn, 256, 1024, 1);
    // 13. ffn out
    split_kernel<<<(M1*DFF/4 + 255)/256, 256>>>(p_ffn, p_ahi, p_alo, M1*DFF/4);
    mma_gemm<<<dim3(4, M1/128), 256>>>(p_ahi, p_alo, p_whi + WO_L2, p_wlo + WO_L2, l2b, p_tmp, 1024, 256, 0);
    // 14. out = LN(tgt2 + t2, norm3)
    ln_kernel<<<M1, 256>>>(p_tgt2, p_tmp, n3g, n3b, out);
}

// round 10
// speedup vs baseline: 3.0008x; 1.0960x over previous
#include <cuda_runtime.h>
#include <cuda_bf16.h>
#include <math.h>
#include <stdint.h>

// ---------------- problem constants ----------------
#define Bq   16
#define LQ   1024
#define Dm   256
#define Hh   8
#define Ll   4
#define Pp   4
#define DFF  1024
#define DH   32
#define LV   5440
#define M1   (Bq*LQ)       // 16384
#define MV   (Bq*LV)       // 87040
#define EPSV 1e-5f

typedef unsigned long long u64;
typedef uint32_t u32;

// ---------------- f32x2 helpers (attention) ----------------
__device__ __forceinline__ u64 pack2(float x, float y) {
    u64 r; asm("mov.b64 %0, {%1, %2};" : "=l"(r) : "f"(x), "f"(y)); return r;
}
__device__ __forceinline__ float2 unpack2(u64 v) {
    float2 f; asm("mov.b64 {%0, %1}, %2;" : "=f"(f.x), "=f"(f.y) : "l"(v)); return f;
}
__device__ __forceinline__ void ffma2(u64& d, u64 a, u64 b) {
    asm("fma.rn.f32x2 %0, %1, %2, %0;" : "+l"(d) : "l"(a), "l"(b));
}
__device__ __forceinline__ void fmul2(u64& d, u64 a) {
    asm("mul.rn.f32x2 %0, %0, %1;" : "+l"(d) : "l"(a));
}

// ---------------- HMMA + cp.async helpers ----------------
__device__ __forceinline__ void mma16816(float* c, const u32* a, const u32* b) {
    asm volatile(
        "mma.sync.aligned.m16n8k16.row.col.f32.bf16.bf16.f32 "
        "{%0,%1,%2,%3}, {%4,%5,%6,%7}, {%8,%9}, {%0,%1,%2,%3};"
        : "+f"(c[0]), "+f"(c[1]), "+f"(c[2]), "+f"(c[3])
        : "r"(a[0]), "r"(a[1]), "r"(a[2]), "r"(a[3]), "r"(b[0]), "r"(b[1]));
}
__device__ __forceinline__ u32 smem_u32(const void* p) {
    u32 a;
    asm("{ .reg .u64 t; cvta.to.shared.u64 t, %1; cvt.u32.u64 %0, t; }" : "=r"(a) : "l"(p));
    return a;
}
__device__ __forceinline__ void cpa16(u32 s, const void* g) {
    asm volatile("cp.async.cg.shared.global [%0], [%1], 16;" :: "r"(s), "l"(g));
}

// ---------------- scratch (static device, no allocs) ----------------
__device__ float g_qk  [M1*512];
__device__ float g_v   [M1*Dm];
__device__ float g_tmp [M1*Dm];
__device__ float g_tgt [M1*Dm];
__device__ float g_tgt2[M1*Dm];
__device__ float g_value[(size_t)MV*Dm];
__device__ float g_off [M1*256];
__device__ float g_attw[M1*128];

#define AMAX ((size_t)MV*Dm)
__device__ __nv_bfloat16 g_ahi[AMAX];
__device__ __nv_bfloat16 g_alo[AMAX];
__device__ __nv_bfloat16 g_bhi[M1*DFF];
__device__ __nv_bfloat16 g_blo[M1*DFF];
#define WTOT 1015808
__device__ __nv_bfloat16 g_whi[WTOT];
__device__ __nv_bfloat16 g_wlo[WTOT];

#define WO_IN   0
#define WO_INV  131072
#define WO_OW   196608
#define WO_VW   262144
#define WO_OFF  327680
#define WO_AW   393216
#define WO_OP   425984
#define WO_L1   491520
#define WO_L2   753664

// ---------------- fp32 -> (bf16 hi, bf16 lo) split ----------------
__device__ __forceinline__ void split1(float x, __nv_bfloat16& h, __nv_bfloat16& l) {
    h = __float2bfloat16(x);
    l = __float2bfloat16(x - __bfloat162float(h));
}
__global__ void split_kernel(const float* __restrict__ x,
                             __nv_bfloat16* __restrict__ hi,
                             __nv_bfloat16* __restrict__ lo, int n4) {
    int i = blockIdx.x * blockDim.x + threadIdx.x;
    if (i < n4) {
        float4 v = ((const float4*)x)[i];
        __nv_bfloat16 h0,h1,h2,h3,l0,l1,l2,l3;
        split1(v.x,h0,l0); split1(v.y,h1,l1); split1(v.z,h2,l2); split1(v.w,h3,l3);
        ((__nv_bfloat162*)hi)[2*i]   = __nv_bfloat162(h0,h1);
        ((__nv_bfloat162*)hi)[2*i+1] = __nv_bfloat162(h2,h3);
        ((__nv_bfloat162*)lo)[2*i]   = __nv_bfloat162(l0,l1);
        ((__nv_bfloat162*)lo)[2*i+1] = __nv_bfloat162(l2,l3);
    }
}
__global__ void add_split_kernel(const float* __restrict__ a, const float* __restrict__ b,
                                 __nv_bfloat16* __restrict__ hi,
                                 __nv_bfloat16* __restrict__ lo, int n4) {
    int i = blockIdx.x * blockDim.x + threadIdx.x;
    if (i < n4) {
        float4 av = ((const float4*)a)[i];
        float4 bv = ((const float4*)b)[i];
        float4 v = make_float4(av.x+bv.x, av.y+bv.y, av.z+bv.z, av.w+bv.w);
        __nv_bfloat16 h0,h1,h2,h3,l0,l1,l2,l3;
        split1(v.x,h0,l0); split1(v.y,h1,l1); split1(v.z,h2,l2); split1(v.w,h3,l3);
        ((__nv_bfloat162*)hi)[2*i]   = __nv_bfloat162(h0,h1);
        ((__nv_bfloat162*)hi)[2*i+1] = __nv_bfloat162(h2,h3);
        ((__nv_bfloat162*)lo)[2*i]   = __nv_bfloat162(l0,l1);
        ((__nv_bfloat162*)lo)[2*i+1] = __nv_bfloat162(l2,l3);
    }
}

// ---------------- split-bf16 HMMA GEMM, cp.async double-buffered ----------------
// C = (Ahi+Alo)(MxK) @ (Whi+Wlo)(NxK)^T + bias; grid=(N/64, M/128), 256 thr.
// smem per buffer: Ah 10240 | Al 10240 | Bh 5120 | Bl 5120 = 30720 B; x2 buffers.
#define SSTR 40
#define BUFB 30720
#define SMT  (2*BUFB)

__global__ __launch_bounds__(256) void mma_gemm(
    const __nv_bfloat16* __restrict__ Ahi, const __nv_bfloat16* __restrict__ Alo,
    const __nv_bfloat16* __restrict__ Whi, const __nv_bfloat16* __restrict__ Wlo,
    const float* __restrict__ bias, float* __restrict__ C,
    __nv_bfloat16* __restrict__ Chi, __nv_bfloat16* __restrict__ Clo,
    int K, int N, int relu, int splitout)
{
    extern __shared__ char smem[];
    const u32 sb = smem_u32(smem);

    const int tid  = threadIdx.x;
    const int lane = tid & 31, wid = tid >> 5;
    const int wm = wid >> 1, wn = wid & 1;
    const int m0 = blockIdx.y * 128, n0 = blockIdx.x * 64;
    const int r = lane >> 2, q = (lane & 3) * 2;

    float acc[2][4][4];
    #pragma unroll
    for (int mi = 0; mi < 2; mi++)
        #pragma unroll
        for (int ni = 0; ni < 4; ni++)
            #pragma unroll
            for (int c = 0; c < 4; c++) acc[mi][ni][c] = 0.f;

    // staging indices
    const int arow = tid >> 2;              // + it*64
    const int ac4  = tid & 3;
    const int brow = tid >> 2;
    const int bc4  = tid & 3;

    const int nch = K >> 5;

    // ---- stage helper (lambda) ----
    auto stage = [&](int buf, int kc) {
        u32 oah = sb + buf * BUFB;
        u32 oal = oah + 10240;
        u32 obh = oah + 20480;
        u32 obl = oah + 25600;
        #pragma unroll
        for (int it = 0; it < 2; it++) {
            int row = arow + it * 64;
            size_t gof = (size_t)(m0 + row) * K + kc + ac4 * 8;
            u32 so = (u32)(row * SSTR + ac4 * 8) * 2;
            cpa16(oah + so, Ahi + gof);
            cpa16(oal + so, Alo + gof);
        }
        {
            size_t gof = (size_t)(n0 + brow) * K + kc + bc4 * 8;
            u32 so = (u32)(brow * SSTR + bc4 * 8) * 2;
            cpa16(obh + so, Whi + gof);
            cpa16(obl + so, Wlo + gof);
        }
        asm volatile("cp.async.commit_group;" ::: "memory");
    };

    stage(0, 0);
    int buf = 0;
    for (int ck = 0; ck < nch; ck++) {
        const bool more = (ck + 1 < nch);
        if (more) stage(buf ^ 1, (ck + 1) << 5);
        if (more) asm volatile("cp.async.wait_group 1;" ::: "memory");
        else      asm volatile("cp.async.wait_group 0;" ::: "memory");
        __syncthreads();

        const __nv_bfloat16* sAh = (const __nv_bfloat16*)(smem + buf * BUFB);
        const __nv_bfloat16* sAl = (const __nv_bfloat16*)(smem + buf * BUFB + 10240);
        const __nv_bfloat16* sBh = (const __nv_bfloat16*)(smem + buf * BUFB + 20480);
        const __nv_bfloat16* sBl = (const __nv_bfloat16*)(smem + buf * BUFB + 25600);

        #pragma unroll
        for (int ks = 0; ks < 32; ks += 16) {
            u32 ah[2][4], al[2][4];
            #pragma unroll
            for (int mi = 0; mi < 2; mi++) {
                int base = wm*32 + mi*16;
                int o00 = (base + r    ) * SSTR + ks + q;
                int o10 = (base + r + 8) * SSTR + ks + q;
                ah[mi][0] = *(const u32*)&sAh[o00];
                ah[mi][1] = *(const u32*)&sAh[o10];
                ah[mi][2] = *(const u32*)&sAh[o00 + 8];
                ah[mi][3] = *(const u32*)&sAh[o10 + 8];
                al[mi][0] = *(const u32*)&sAl[o00];
                al[mi][1] = *(const u32*)&sAl[o10];
                al[mi][2] = *(const u32*)&sAl[o00 + 8];
                al[mi][3] = *(const u32*)&sAl[o10 + 8];
            }
            u32 bh[4][2], bl[4][2];
            #pragma unroll
            for (int ni = 0; ni < 4; ni++) {
                int base = wn*32 + ni*8;
                int o = (base + r) * SSTR + ks + q;
                bh[ni][0] = *(const u32*)&sBh[o];
                bh[ni][1] = *(const u32*)&sBh[o + 8];
                bl[ni][0] = *(const u32*)&sBl[o];
                bl[ni][1] = *(const u32*)&sBl[o + 8];
            }
            #pragma unroll
            for (int mi = 0; mi < 2; mi++)
                #pragma unroll
                for (int ni = 0; ni < 4; ni++) {
                    mma16816(acc[mi][ni], ah[mi], bh[ni]);
                    mma16816(acc[mi][ni], ah[mi], bl[ni]);
                    mma16816(acc[mi][ni], al[mi], bh[ni]);
                }
        }
        __syncthreads();
        buf ^= 1;
    }

    // ---- epilogue ----
    #pragma unroll
    for (int mi = 0; mi < 2; mi++) {
        int row0 = m0 + wm*32 + mi*16 + r;
        #pragma unroll
        for (int ni = 0; ni < 4; ni++) {
            int col = n0 + wn*32 + ni*8 + q;
            float2 bv = *(const float2*)(bias + col);
            float2 v0 = make_float2(acc[mi][ni][0] + bv.x, acc[mi][ni][1] + bv.y);
            float2 v1 = make_float2(acc[mi][ni][2] + bv.x, acc[mi][ni][3] + bv.y);
            if (relu) {
                v0.x = fmaxf(v0.x, 0.f); v0.y = fmaxf(v0.y, 0.f);
                v1.x = fmaxf(v1.x, 0.f); v1.y = fmaxf(v1.y, 0.f);
            }
            if (splitout) {
                __nv_bfloat16 h0,l0,h1,l1,h2,l2,h3,l3;
                split1(v0.x,h0,l0); split1(v0.y,h1,l1);
                split1(v1.x,h2,l2); split1(v1.y,h3,l3);
                *(__nv_bfloat162*)&Chi[(size_t)row0     * N + col] = __nv_bfloat162(h0,h1);
                *(__nv_bfloat162*)&Clo[(size_t)row0     * N + col] = __nv_bfloat162(l0,l1);
                *(__nv_bfloat162*)&Chi[(size_t)(row0+8) * N + col] = __nv_bfloat162(h2,h3);
                *(__nv_bfloat162*)&Clo[(size_t)(row0+8) * N + col] = __nv_bfloat162(l2,l3);
            } else {
                *(float2*)(C + (size_t)row0     * N + col) = v0;
                *(float2*)(C + (size_t)(row0+8) * N + col) = v1;
            }
        }
    }
}

// ---------------- flash attention (f32x2 core, split-bf16 output) ----------------
#define ATQ 128
#define KC  32
__global__ __launch_bounds__(ATQ) void attn_kernel(
    const float* __restrict__ QK, const float* __restrict__ V,
    __nv_bfloat16* __restrict__ Ohi, __nv_bfloat16* __restrict__ Olo)
{
    __shared__ float Ks[KC][32];
    __shared__ float Vs[KC][32];
    __shared__ float Ss[ATQ][KC + 1];
    const int t = threadIdx.x;
    const int bh = blockIdx.y, b = bh >> 3, h = bh & 7;
    const int q = blockIdx.x * ATQ + t;

    const float4* qp = (const float4*)(QK + ((size_t)(b*LQ + q))*512 + h*DH);
    float4 qv[8];
    #pragma unroll
    for (int i = 0; i < 8; i++) qv[i] = qp[i];
    const u64* q2 = (const u64*)qv;

    u64 o2[16];
    #pragma unroll
    for (int i = 0; i < 16; i++) o2[i] = 0ull;
    float m = -1e30f, l = 0.f;
    const float scale = 0.17677669529663687f;

    const int sr0 = t >> 3;
    const int sc  = t & 7;

    for (int kc = 0; kc < LQ; kc += KC) {
        #pragma unroll
        for (int ph = 0; ph < 2; ph++) {
            int row = sr0 + ph*16;
            const float4* kp = (const float4*)(QK + ((size_t)(b*LQ + kc + row))*512 + 256 + h*DH);
            const float4* vp = (const float4*)(V  + ((size_t)(b*LQ + kc + row))*Dm  + h*DH);
            *((float4*)Ks[row] + sc) = kp[sc];
            *((float4*)Vs[row] + sc) = vp[sc];
        }
        __syncthreads();

        float cmax = -1e30f;
        #pragma unroll 8
        for (int j = 0; j < KC; j++) {
            const u64* kk = (const u64*)Ks[j];
            u64 d2 = 0ull;
            #pragma unroll
            for (int i = 0; i < 16; i++) ffma2(d2, q2[i], kk[i]);
            float2 dd = unpack2(d2);
            float d = (dd.x + dd.y) * scale;
            Ss[t][j] = d;
            cmax = fmaxf(cmax, d);
        }
        float mnew = fmaxf(m, cmax);
        float corr = __expf(m - mnew);
        l *= corr;
        u64 cc = pack2(corr, corr);
        #pragma unroll
        for (int i = 0; i < 16; i++) fmul2(o2[i], cc);

        #pragma unroll 4
        for (int j = 0; j < KC; j++) {
            float p = __expf(Ss[t][j] - mnew);
            l += p;
            u64 pp = pack2(p, p);
            const u64* vv = (const u64*)Vs[j];
            #pragma unroll
            for (int i = 0; i < 16; i++) ffma2(o2[i], pp, vv[i]);
        }
        m = mnew;
        __syncthreads();
    }

    float inv = 1.f / l;
    u64 iv = pack2(inv, inv);
    size_t base = ((size_t)(b*LQ + q))*Dm + h*DH;
    #pragma unroll
    for (int i = 0; i < 16; i++) {
        fmul2(o2[i], iv);
        float2 f = unpack2(o2[i]);
        __nv_bfloat16 h0,l0,h1,l1;
        split1(f.x,h0,l0); split1(f.y,h1,l1);
        *(__nv_bfloat162*)&Ohi[base + 2*i] = __nv_bfloat162(h0,h1);
        *(__nv_bfloat162*)&Olo[base + 2*i] = __nv_bfloat162(l0,l1);
    }
}

// ---------------- layernorm(a + b) * g + beta (optional split out) ----------------
template<int SPLIT>
__global__ __launch_bounds__(256) void ln_kernel_t(
    const float* __restrict__ a, const float* __restrict__ b,
    const float* __restrict__ g, const float* __restrict__ be,
    float* __restrict__ out,
    __nv_bfloat16* __restrict__ ohi, __nv_bfloat16* __restrict__ olo)
{
    __shared__ float red[8];
    int row = blockIdx.x, t = threadIdx.x;
    float x = a[(size_t)row*Dm + t] + b[(size_t)row*Dm + t];

    float s = x;
    #pragma unroll
    for (int o = 16; o; o >>= 1) s += __shfl_xor_sync(0xffffffffu, s, o);
    if ((t & 31) == 0) red[t >> 5] = s;
    __syncthreads();
    float tot = 0.f;
    #pragma unroll
    for (int i = 0; i < 8; i++) tot += red[i];
    float mean = tot * (1.f / Dm);
    float d0 = x - mean;
    __syncthreads();

    float sq = d0 * d0;
    #pragma unroll
    for (int o = 16; o; o >>= 1) sq += __shfl_xor_sync(0xffffffffu, sq, o);
    if ((t & 31) == 0) red[t >> 5] = sq;
    __syncthreads();
    float tot2 = 0.f;
    #pragma unroll
    for (int i = 0; i < 8; i++) tot2 += red[i];
    float var = tot2 * (1.f / Dm);

    float y = d0 * rsqrtf(var + EPSV) * g[t] + be[t];
    out[(size_t)row*Dm + t] = y;
    if (SPLIT) {
        __nv_bfloat16 h, lo_;
        split1(y, h, lo_);
        ohi[(size_t)row*Dm + t] = h;
        olo[(size_t)row*Dm + t] = lo_;
    }
}

// ---------------- deformable sampler (attw softmax fused, split out) ----------------
__global__ __launch_bounds__(256) void sampler_kernel(
    const float* __restrict__ refp,
    const float* __restrict__ off,
    const float* __restrict__ attw,
    const float* __restrict__ value,
    __nv_bfloat16* __restrict__ shi, __nv_bfloat16* __restrict__ slo)
{
    int bq = blockIdx.x;
    int b = bq >> 10;
    int t = threadIdx.x;
    int h = t >> 5, lane = t & 31;

    float logit = (lane < 16) ? attw[(size_t)bq*128 + h*16 + lane] : -1e30f;
    float mx = logit;
    #pragma unroll
    for (int o = 16; o; o >>= 1) mx = fmaxf(mx, __shfl_xor_sync(0xffffffffu, mx, o));
    float e = (lane < 16) ? __expf(logit - mx) : 0.f;
    float sum = e;
    #pragma unroll
    for (int o = 16; o; o >>= 1) sum += __shfl_xor_sync(0xffffffffu, sum, o);
    float aw_lane = e / sum;

    const int wls[4]    = {64, 32, 16, 8};
    const int hls[4]    = {64, 32, 16, 8};
    const int starts[4] = {0, 4096, 5120, 5376};

    const float* rp = refp + ((size_t)bq * Ll) * 2;
    float acc = 0.f;

    #pragma unroll
    for (int l = 0; l < Ll; l++) {
        int wl = wls[l], hl = hls[l], st = starts[l];
        float rx = rp[l*2 + 0];
        float ry = rp[l*2 + 1];
        #pragma unroll
        for (int p = 0; p < Pp; p++) {
            int n = (h*Ll + l)*Pp + p;
            float ox = off[(size_t)bq*256 + n*2 + 0];
            float oy = off[(size_t)bq*256 + n*2 + 1];
            float x = (rx + ox / (float)wl) * (float)wl - 0.5f;
            float y = (ry + oy / (float)hl) * (float)hl - 0.5f;
            float x0f = floorf(x), y0f = floorf(y);
            float lx = x - x0f, ly = y - y0f;
            int x0 = (int)x0f, y0 = (int)y0f;
            float aw = __shfl_sync(0xffffffffu, aw_lane, l*Pp + p);

            float g00 = 0.f, g01 = 0.f, g10 = 0.f, g11 = 0.f;
            if (x0   >= 0 && x0   < wl && y0   >= 0 && y0   < hl)
                g00 = value[((size_t)(b*LV + st + y0*wl + x0))*Dm + h*DH + lane];
            if (x0+1 >= 0 && x0+1 < wl && y0   >= 0 && y0   < hl)
                g01 = value[((size_t)(b*LV + st + y0*wl + x0+1))*Dm + h*DH + lane];
            if (x0   >= 0 && x0   < wl && y0+1 >= 0 && y0+1 < hl)
                g10 = value[((size_t)(b*LV + st + (y0+1)*wl + x0))*Dm + h*DH + lane];
            if (x0+1 >= 0 && x0+1 < wl && y0+1 >= 0 && y0+1 < hl)
                g11 = value[((size_t)(b*LV + st + (y0+1)*wl + x0+1))*Dm + h*DH + lane];

            float sv = g00*(1.f-lx)*(1.f-ly) + g01*lx*(1.f-ly)
                     + g10*(1.f-lx)*ly       + g11*lx*ly;
            acc += aw * sv;
        }
    }
    __nv_bfloat16 hh, ll;
    split1(acc, hh, ll);
    shi[(size_t)bq*Dm + h*DH + lane] = hh;
    slo[(size_t)bq*Dm + h*DH + lane] = ll;
}

// ---------------- launch ----------------
extern "C" void kernel_launch(void* const* d_in, const int* in_sizes, int n_in,
                              void* d_out, int out_size) {
    const float* tgt  = (const float*)d_in[0];
    const float* qpos = (const float*)d_in[1];
    const float* refp = (const float*)d_in[2];
    const float* src  = (const float*)d_in[3];
    const float* in_w = (const float*)d_in[4];
    const float* in_b = (const float*)d_in[5];
    const float* ow   = (const float*)d_in[6];
    const float* ob   = (const float*)d_in[7];
    const float* n2g  = (const float*)d_in[8];
    const float* n2b  = (const float*)d_in[9];
    const float* vw   = (const float*)d_in[10];
    const float* vb   = (const float*)d_in[11];
    const float* offw = (const float*)d_in[12];
    const float* offb = (const float*)d_in[13];
    const float* aww  = (const float*)d_in[14];
    const float* awb  = (const float*)d_in[15];
    const float* opw  = (const float*)d_in[16];
    const float* opb  = (const float*)d_in[17];
    const float* n1g  = (const float*)d_in[18];
    const float* n1b  = (const float*)d_in[19];
    const float* l1w  = (const float*)d_in[20];
    const float* l1b  = (const float*)d_in[21];
    const float* l2w  = (const float*)d_in[22];
    const float* l2b  = (const float*)d_in[23];
    const float* n3g  = (const float*)d_in[24];
    const float* n3b  = (const float*)d_in[25];
    float* out = (float*)d_out;

    float *p_qk, *p_v, *p_tmp, *p_tgt, *p_tgt2, *p_value, *p_off, *p_attw;
    __nv_bfloat16 *p_ahi, *p_alo, *p_bhi, *p_blo, *p_whi, *p_wlo;
    cudaGetSymbolAddress((void**)&p_qk,   g_qk);
    cudaGetSymbolAddress((void**)&p_v,    g_v);
    cudaGetSymbolAddress((void**)&p_tmp,  g_tmp);
    cudaGetSymbolAddress((void**)&p_tgt,  g_tgt);
    cudaGetSymbolAddress((void**)&p_tgt2, g_tgt2);
    cudaGetSymbolAddress((void**)&p_value,g_value);
    cudaGetSymbolAddress((void**)&p_off,  g_off);
    cudaGetSymbolAddress((void**)&p_attw, g_attw);
    cudaGetSymbolAddress((void**)&p_ahi,  g_ahi);
    cudaGetSymbolAddress((void**)&p_alo,  g_alo);
    cudaGetSymbolAddress((void**)&p_bhi,  g_bhi);
    cudaGetSymbolAddress((void**)&p_blo,  g_blo);
    cudaGetSymbolAddress((void**)&p_whi,  g_whi);
    cudaGetSymbolAddress((void**)&p_wlo,  g_wlo);

    cudaFuncSetAttribute(mma_gemm, cudaFuncAttributeMaxDynamicSharedMemorySize, SMT);

    const int n4 = M1 * Dm / 4;

    // ---- weight splits ----
    #define SPL(src_, off_, n_) split_kernel<<<((n_)/4 + 255)/256, 256>>>(src_, p_whi + (off_), p_wlo + (off_), (n_)/4)
    SPL(in_w, WO_IN,  768*256);
    SPL(ow,   WO_OW,  65536);
    SPL(vw,   WO_VW,  65536);
    SPL(offw, WO_OFF, 65536);
    SPL(aww,  WO_AW,  32768);
    SPL(opw,  WO_OP,  65536);
    SPL(l1w,  WO_L1,  262144);
    SPL(l2w,  WO_L2,  262144);
    #undef SPL

    // 1. q = tgt + qpos -> bf16 split
    add_split_kernel<<<(n4 + 255)/256, 256>>>(tgt, qpos, p_ahi, p_alo, n4);
    // 2. [Q|K] = q @ in_w[0:512].T + b
    mma_gemm<<<dim3(8, M1/128), 256, SMT>>>(p_ahi, p_alo, p_whi + WO_IN, p_wlo + WO_IN, in_b, p_qk, 0, 0, 256, 512, 0, 0);
    // 3. V = tgt @ in_w[512:768].T + b
    split_kernel<<<(n4 + 255)/256, 256>>>(tgt, p_ahi, p_alo, n4);
    mma_gemm<<<dim3(4, M1/128), 256, SMT>>>(p_ahi, p_alo, p_whi + WO_INV, p_wlo + WO_INV, in_b + 512, p_v, 0, 0, 256, 256, 0, 0);
    // 4. attention (writes split att directly)
    attn_kernel<<<dim3(LQ/ATQ, Bq*Hh), ATQ>>>(p_qk, p_v, p_ahi, p_alo);
    // 5. out_proj
    mma_gemm<<<dim3(4, M1/128), 256, SMT>>>(p_ahi, p_alo, p_whi + WO_OW, p_wlo + WO_OW, ob, p_tmp, 0, 0, 256, 256, 0, 0);
    // 6. tgt = LN(tgt + tgt2, norm2)
    ln_kernel_t<0><<<M1, 256>>>(tgt, p_tmp, n2g, n2b, p_tgt, 0, 0);
    // 7. q2 = tgt + qpos -> off + attw projections
    add_split_kernel<<<(n4 + 255)/256, 256>>>(p_tgt, qpos, p_ahi, p_alo, n4);
    mma_gemm<<<dim3(4, M1/128), 256, SMT>>>(p_ahi, p_alo, p_whi + WO_OFF, p_wlo + WO_OFF, offb, p_off, 0, 0, 256, 256, 0, 0);
    mma_gemm<<<dim3(2, M1/128), 256, SMT>>>(p_ahi, p_alo, p_whi + WO_AW, p_wlo + WO_AW, awb, p_attw, 0, 0, 256, 128, 0, 0);
    // 8. value = src @ value_w.T + b
    split_kernel<<<((int)(MV*(size_t)Dm/4) + 255)/256, 256>>>(src, p_ahi, p_alo, (int)(MV*(size_t)Dm/4));
    mma_gemm<<<dim3(4, MV/128), 256, SMT>>>(p_ahi, p_alo, p_whi + WO_VW, p_wlo + WO_VW, vb, p_value, 0, 0, 256, 256, 0, 0);
    // 9. sampler (writes split samp directly)
    sampler_kernel<<<M1, 256>>>(refp, p_off, p_attw, p_value, p_ahi, p_alo);
    // 10. outp proj
    mma_gemm<<<dim3(4, M1/128), 256, SMT>>>(p_ahi, p_alo, p_whi + WO_OP, p_wlo + WO_OP, opb, p_tmp, 0, 0, 256, 256, 0, 0);
    // 11. tgt2 = LN(tgt + t, norm1) -> fp32 + split
    ln_kernel_t<1><<<M1, 256>>>(p_tgt, p_tmp, n1g, n1b, p_tgt2, p_ahi, p_alo);
    // 12. ffn mid = relu(tgt2 @ l1w.T + b) -> split output
    mma_gemm<<<dim3(16, M1/128), 256, SMT>>>(p_ahi, p_alo, p_whi + WO_L1, p_wlo + WO_L1, l1b, 0, p_bhi, p_blo, 256, 1024, 1, 1);
    // 13. ffn out
    mma_gemm<<<dim3(4, M1/128), 256, SMT>>>(p_bhi, p_blo, p_whi + WO_L2, p_wlo + WO_L2, l2b, p_tmp, 0, 0, 1024, 256, 0, 0);
    // 14. out = LN(tgt2 + t2, norm3)
    ln_kernel_t<0><<<M1, 256>>>(p_tgt2, p_tmp, n3g, n3b, out, 0, 0);
}